// round 12
// baseline (speedup 1.0000x reference)
#include <cuda_runtime.h>
#include <cuda_fp16.h>

#define NN 50000
#define HD 128
#define EE 640000
#define GG 128
#define SPLITR 37888                     // 296 * 128 rows = exactly 2 waves

typedef unsigned int u32;
typedef unsigned short u16;
typedef unsigned long long u64;

// Scratch buffers
__device__ float g_bufA[NN * HD];
__device__ float g_bufB[NN * HD];
__device__ float g_bufC[NN * HD];
// Pre-split W: [layer][hi/lo][16384 halves], swizzled smem image.
__device__ __align__(16) u16 g_wsp[4 * 2 * 16384];
// CSR-by-dst scratch
__device__ int g_rp[NN + 1];
__device__ int g_cur[NN];
__device__ int g_ssrc[EE];
__device__ int g_bsum[256];

#define SCAN_B 196

__device__ __forceinline__ u32 smem_u32(const void* p) {
    u32 a;
    asm("{ .reg .u64 t; cvta.to.shared.u64 t, %1; cvt.u32.u64 %0, t; }"
        : "=r"(a) : "l"(p));
    return a;
}
__device__ __forceinline__ void mma_f16(float* d, const u32* a, const u32* b) {
    asm("mma.sync.aligned.m16n8k16.row.col.f32.f16.f16.f32 "
        "{%0,%1,%2,%3}, {%4,%5,%6,%7}, {%8,%9}, {%0,%1,%2,%3};"
        : "+f"(d[0]), "+f"(d[1]), "+f"(d[2]), "+f"(d[3])
        : "r"(a[0]), "r"(a[1]), "r"(a[2]), "r"(a[3]), "r"(b[0]), "r"(b[1]));
}
__device__ __forceinline__ void ldsm4(u32* r, u32 addr) {
    asm volatile("ldmatrix.sync.aligned.m8n8.x4.shared.b16 {%0,%1,%2,%3}, [%4];"
                 : "=r"(r[0]), "=r"(r[1]), "=r"(r[2]), "=r"(r[3]) : "r"(addr));
}
__device__ __forceinline__ void cp16(u32 smem, const void* g) {
    asm volatile("cp.async.cg.shared.global [%0], [%1], 16;"
                 :: "r"(smem), "l"(g) : "memory");
}
__device__ __forceinline__ int swz_idx(int r, int kh) {
    return r * 32 + ((((kh >> 3) ^ ((r >> 1) & 3)) << 3) | (kh & 7));
}

// ---------------------------------------------------------------------------
// W prep: f16 hi/lo split, transposed [n][k], k-chunked, swizzled.
// ---------------------------------------------------------------------------
__global__ void prep_w(const float* __restrict__ W1, const float* __restrict__ W2,
                       const float* __restrict__ W3, const float* __restrict__ W4,
                       u16* __restrict__ out)
{
    int t = blockIdx.x * 256 + threadIdx.x;
    int layer = t >> 14, e = t & 16383;
    int k = e >> 7, n = e & 127;
    const float* W = layer == 0 ? W1 : layer == 1 ? W2 : layer == 2 ? W3 : W4;
    float v = W[k * HD + n];
    __half hi = __float2half_rn(v);
    __half lo = __float2half_rn(v - __half2float(hi));
    int ch = k >> 5, kh = k & 31;
    int idx = ch * 4096 + swz_idx(n, kh);
    int base = layer * 32768;
    out[base + idx]         = __half_as_ushort(hi);
    out[base + 16384 + idx] = __half_as_ushort(lo);
}

// ---------------------------------------------------------------------------
// CSR build
// ---------------------------------------------------------------------------
__global__ void csr_zero(int* __restrict__ cnt)
{
    int t = blockIdx.x * blockDim.x + threadIdx.x;
    if (t < NN) cnt[t] = 0;
}
__global__ void csr_hist(const int* __restrict__ ei, int* __restrict__ cnt)
{
    int e = blockIdx.x * blockDim.x + threadIdx.x;
    if (e < EE) atomicAdd(cnt + __ldg(ei + 2 * e + 1), 1);
}
__global__ void csr_scan1(const int* __restrict__ cnt, int* __restrict__ bsum)
{
    __shared__ int s[256];
    int t = threadIdx.x, i = blockIdx.x * 256 + t;
    s[t] = (i < NN) ? cnt[i] : 0;
    __syncthreads();
    for (int o = 128; o > 0; o >>= 1) {
        if (t < o) s[t] += s[t + o];
        __syncthreads();
    }
    if (t == 0) bsum[blockIdx.x] = s[0];
}
__global__ void csr_scan2(int* __restrict__ bsum, int* __restrict__ rp)
{
    if (threadIdx.x == 0) {
        int run = 0;
        for (int b = 0; b < SCAN_B; b++) {
            int v = bsum[b];
            bsum[b] = run;
            run += v;
        }
        rp[NN] = run;
    }
}
__global__ void csr_scan3(const int* __restrict__ cnt, const int* __restrict__ bsum,
                          int* __restrict__ rp, int* __restrict__ cur)
{
    __shared__ int s[256];
    int t = threadIdx.x, i = blockIdx.x * 256 + t;
    int c = (i < NN) ? cnt[i] : 0;
    s[t] = c;
    __syncthreads();
    for (int o = 1; o < 256; o <<= 1) {
        int v = (t >= o) ? s[t - o] : 0;
        __syncthreads();
        s[t] += v;
        __syncthreads();
    }
    if (i < NN) {
        int excl = bsum[blockIdx.x] + s[t] - c;
        rp[i] = excl;
        cur[i] = excl;
    }
}
__global__ void csr_place(const int* __restrict__ ei, int* __restrict__ cur,
                          int* __restrict__ ssrc)
{
    int e = blockIdx.x * blockDim.x + threadIdx.x;
    if (e >= EE) return;
    int src = __ldg(ei + 2 * e);
    int dst = __ldg(ei + 2 * e + 1);
    int pos = atomicAdd(cur + dst, 1);
    ssrc[pos] = src;
}

// ---------------------------------------------------------------------------
// Atomic-free aggregate over dst rows [n0, n1):
// out[d,:] = h[d,:] + sum_{e in row d} h[ssrc[e],:]
// NOTE: gathers arbitrary rows of h -> h must be fully written AND not being
// overwritten anywhere while this runs.
// ---------------------------------------------------------------------------
__global__ void __launch_bounds__(256) csr_agg(
    const float* __restrict__ h, const int* __restrict__ rp,
    const int* __restrict__ ssrc, float* __restrict__ out, int n0, int n1)
{
    int d = n0 + ((blockIdx.x * blockDim.x + threadIdx.x) >> 5);
    if (d >= n1) return;
    int lane = threadIdx.x & 31;
    float4 acc = __ldg((const float4*)(h + (size_t)d * HD) + lane);
    int e = __ldg(rp + d), e1 = __ldg(rp + d + 1);
    for (; e + 4 <= e1; e += 4) {
        int s0 = __ldg(ssrc + e + 0);
        int s1 = __ldg(ssrc + e + 1);
        int s2 = __ldg(ssrc + e + 2);
        int s3 = __ldg(ssrc + e + 3);
        float4 v0 = __ldg((const float4*)(h + (size_t)s0 * HD) + lane);
        float4 v1 = __ldg((const float4*)(h + (size_t)s1 * HD) + lane);
        float4 v2 = __ldg((const float4*)(h + (size_t)s2 * HD) + lane);
        float4 v3 = __ldg((const float4*)(h + (size_t)s3 * HD) + lane);
        acc.x += (v0.x + v1.x) + (v2.x + v3.x);
        acc.y += (v0.y + v1.y) + (v2.y + v3.y);
        acc.z += (v0.z + v1.z) + (v2.z + v3.z);
        acc.w += (v0.w + v1.w) + (v2.w + v3.w);
    }
    for (; e < e1; ++e) {
        int s = __ldg(ssrc + e);
        float4 v = __ldg((const float4*)(h + (size_t)s * HD) + lane);
        acc.x += v.x; acc.y += v.y; acc.z += v.z; acc.w += v.w;
    }
    *((float4*)(out + (size_t)d * HD) + lane) = acc;
}

// ---------------------------------------------------------------------------
// Smem layout (bytes). Full-K resident.
// ---------------------------------------------------------------------------
#define SM_BB  0
#define SM_SC  512
#define SM_OF  1024
#define SM_W   1536
#define SM_A   (SM_W + 65536)
#define SM_TOT (SM_A + 65536)            // 132608 B -> 1 CTA/SM, 16 warps

// ---------------------------------------------------------------------------
// Split-f16 GEMM (3xF16) over rows [rbase, rbase + 128*gridDim.x) clipped to M.
// ---------------------------------------------------------------------------
template <bool DO_BN>
__global__ void __launch_bounds__(512, 1) gemm_f16(
    const float* __restrict__ A, const u16* __restrict__ wsp,
    const float* __restrict__ bias, const float* __restrict__ gam,
    const float* __restrict__ bet, const float* __restrict__ mmean,
    const float* __restrict__ mvar, float* __restrict__ out, int rbase, int M)
{
    extern __shared__ char sm[];
    const u32 sb = smem_u32(sm);
    float* const bbp = (float*)(sm + SM_BB);
    float* const scp = (float*)(sm + SM_SC);
    float* const ofp = (float*)(sm + SM_OF);

    const int tid = threadIdx.x, wid = tid >> 5, lane = tid & 31;
    const int g = lane >> 2, q = lane & 3;
    const int wm = wid & 3, wn = wid >> 2;
    const int row0 = rbase + blockIdx.x * 128;

    if (tid < 128) {
        bbp[tid] = bias[tid];
        float s = 1.f, o = 0.f;
        if (DO_BN) {
            s = gam[tid] * rsqrtf(mvar[tid] + 1e-3f);
            o = bet[tid] - mmean[tid] * s;
        }
        scp[tid] = s;
        ofp[tid] = o;
    }

#pragma unroll
    for (int i = 0; i < 8; i++) {
        int idx = tid + i * 512;
        cp16(sb + SM_W + idx * 16, (const char*)wsp + idx * 16);
    }

    {
        const int j4 = lane * 4;
        const int ch = lane >> 3;
        const int kh = j4 & 31;
#pragma unroll
        for (int i = 0; i < 8; i++) {
            int r = wid * 8 + i;
            int grow = row0 + r;
            float4 v = make_float4(0.f, 0.f, 0.f, 0.f);
            if (grow < M)
                v = *(const float4*)(A + (size_t)grow * HD + j4);
            __half hx = __float2half_rn(v.x), hy = __float2half_rn(v.y),
                   hz = __float2half_rn(v.z), hw = __float2half_rn(v.w);
            union { u16 s[4]; u64 u; } hp, lp;
            hp.s[0] = __half_as_ushort(hx); hp.s[1] = __half_as_ushort(hy);
            hp.s[2] = __half_as_ushort(hz); hp.s[3] = __half_as_ushort(hw);
            lp.s[0] = __half_as_ushort(__float2half_rn(v.x - __half2float(hx)));
            lp.s[1] = __half_as_ushort(__float2half_rn(v.y - __half2float(hy)));
            lp.s[2] = __half_as_ushort(__float2half_rn(v.z - __half2float(hz)));
            lp.s[3] = __half_as_ushort(__float2half_rn(v.w - __half2float(hw)));
            int hidx = swz_idx(r, kh);
            *(u64*)(sm + SM_A + ch * 16384 + hidx * 2) = hp.u;
            *(u64*)(sm + SM_A + ch * 16384 + 8192 + hidx * 2) = lp.u;
        }
    }

    float d[2][4][4];
#pragma unroll
    for (int mt = 0; mt < 2; mt++)
#pragma unroll
        for (int nt = 0; nt < 4; nt++)
#pragma unroll
            for (int c = 0; c < 4; c++) d[mt][nt][c] = 0.f;

    asm volatile("cp.async.commit_group;" ::: "memory");
    asm volatile("cp.async.wait_group 0;" ::: "memory");
    __syncthreads();

#pragma unroll
    for (int ch = 0; ch < 4; ++ch) {
        const u32 abase = sb + SM_A + ch * 16384;
        const u32 wbase = sb + SM_W + ch * 8192;
#pragma unroll
        for (int s = 0; s < 2; ++s) {
            u32 fa_hi[2][4], fa_lo[2][4];
            const int ar = wm * 32 + (lane & 7) + ((lane & 8) ? 8 : 0);
            const int aj = s * 2 + ((lane & 16) ? 1 : 0);
#pragma unroll
            for (int mt = 0; mt < 2; mt++) {
                int r = ar + mt * 16;
                u32 off = (u32)(r * 64 + ((aj ^ ((r >> 1) & 3)) << 4));
                ldsm4(fa_hi[mt], abase + off);
                ldsm4(fa_lo[mt], abase + 8192 + off);
            }
            u32 fb_hi[4][2], fb_lo[4][2];
            const int brb = wn * 32 + ((lane & 16) ? 8 : 0) + (lane & 7);
            const int bj = s * 2 + ((lane & 8) ? 1 : 0);
#pragma unroll
            for (int t = 0; t < 2; t++) {
                int r = brb + t * 16;
                u32 off = (u32)(r * 64 + ((bj ^ ((r >> 1) & 3)) << 4));
                u32 tmp[4];
                ldsm4(tmp, wbase + off);
                fb_hi[2 * t][0] = tmp[0]; fb_hi[2 * t][1] = tmp[1];
                fb_hi[2 * t + 1][0] = tmp[2]; fb_hi[2 * t + 1][1] = tmp[3];
                ldsm4(tmp, wbase + 32768 + off);
                fb_lo[2 * t][0] = tmp[0]; fb_lo[2 * t][1] = tmp[1];
                fb_lo[2 * t + 1][0] = tmp[2]; fb_lo[2 * t + 1][1] = tmp[3];
            }
#pragma unroll
            for (int mt = 0; mt < 2; mt++)
#pragma unroll
                for (int nt = 0; nt < 4; nt++)
                    mma_f16(d[mt][nt], fa_hi[mt], fb_hi[nt]);
#pragma unroll
            for (int mt = 0; mt < 2; mt++)
#pragma unroll
                for (int nt = 0; nt < 4; nt++)
                    mma_f16(d[mt][nt], fa_hi[mt], fb_lo[nt]);
#pragma unroll
            for (int mt = 0; mt < 2; mt++)
#pragma unroll
                for (int nt = 0; nt < 4; nt++)
                    mma_f16(d[mt][nt], fa_lo[mt], fb_hi[nt]);
        }
    }

    const int q2 = q * 2;
#pragma unroll
    for (int mt = 0; mt < 2; mt++) {
        int r0 = row0 + wm * 32 + mt * 16 + g;
#pragma unroll
        for (int nt = 0; nt < 4; nt++) {
            int col = wn * 32 + nt * 8 + q2;
            float s0 = scp[col], s1 = scp[col + 1];
            float o0 = ofp[col], o1 = ofp[col + 1];
            float B0 = bbp[col], B1 = bbp[col + 1];
            float v0 = fmaxf(d[mt][nt][0] + B0, 0.f) * s0 + o0;
            float v1 = fmaxf(d[mt][nt][1] + B1, 0.f) * s1 + o1;
            float v2 = fmaxf(d[mt][nt][2] + B0, 0.f) * s0 + o0;
            float v3 = fmaxf(d[mt][nt][3] + B1, 0.f) * s1 + o1;
            if (r0 < M)
                *(float2*)(out + (size_t)r0 * HD + col) = make_float2(v0, v1);
            if (r0 + 8 < M)
                *(float2*)(out + (size_t)(r0 + 8) * HD + col) = make_float2(v2, v3);
        }
    }
}

// ---------------------------------------------------------------------------
// Final graph readout over nodes [n0, n1): sorted batch -> chunked register
// accumulation, one atomic per group boundary.
// ---------------------------------------------------------------------------
#define SEG_CH 64
__global__ void seg_sum(const float* __restrict__ h,
                        const int* __restrict__ batch,
                        float* __restrict__ out, int n0g, int n1g)
{
    int n0 = n0g + blockIdx.x * SEG_CH;
    if (n0 >= n1g) return;
    int j = threadIdx.x;
    int nend = n0 + SEG_CH;
    if (nend > n1g) nend = n1g;
    float acc = 0.f;
    int cur = __ldg(batch + n0);
    for (int n = n0; n < nend; ++n) {
        int b = __ldg(batch + n);
        if (b != cur) {
            atomicAdd(out + (size_t)cur * HD + j, acc);
            acc = 0.f;
            cur = b;
        }
        acc += __ldg(h + (size_t)n * HD + j);
    }
    atomicAdd(out + (size_t)cur * HD + j, acc);
}

__global__ void zero_out(float* __restrict__ out, int n)
{
    int t = blockIdx.x * blockDim.x + threadIdx.x;
    if (t < n) out[t] = 0.f;
}

extern "C" void kernel_launch(void* const* d_in, const int* in_sizes, int n_in,
                              void* d_out, int out_size)
{
    const float* x   = (const float*)d_in[0];
    const int*   ei  = (const int*)d_in[1];
    const int*   bat = (const int*)d_in[2];
    const float* W1  = (const float*)d_in[3];
    const float* b1  = (const float*)d_in[4];
    const float* g1  = (const float*)d_in[5];
    const float* be1 = (const float*)d_in[6];
    const float* mm1 = (const float*)d_in[7];
    const float* mv1 = (const float*)d_in[8];
    const float* W2  = (const float*)d_in[9];
    const float* b2  = (const float*)d_in[10];
    const float* W3  = (const float*)d_in[11];
    const float* b3  = (const float*)d_in[12];
    const float* g2  = (const float*)d_in[13];
    const float* be2 = (const float*)d_in[14];
    const float* mm2 = (const float*)d_in[15];
    const float* mv2 = (const float*)d_in[16];
    const float* W4  = (const float*)d_in[17];
    const float* b4  = (const float*)d_in[18];
    float* out = (float*)d_out;

    float *bufA, *bufB, *bufC;
    u16* wsp;
    int *rp, *cur, *ssrc, *bsum;
    cudaGetSymbolAddress((void**)&bufA, g_bufA);
    cudaGetSymbolAddress((void**)&bufB, g_bufB);
    cudaGetSymbolAddress((void**)&bufC, g_bufC);
    cudaGetSymbolAddress((void**)&wsp, g_wsp);
    cudaGetSymbolAddress((void**)&rp, g_rp);
    cudaGetSymbolAddress((void**)&cur, g_cur);
    cudaGetSymbolAddress((void**)&ssrc, g_ssrc);
    cudaGetSymbolAddress((void**)&bsum, g_bsum);

    cudaFuncSetAttribute(gemm_f16<true>,
                         cudaFuncAttributeMaxDynamicSharedMemorySize, SM_TOT);
    cudaFuncSetAttribute(gemm_f16<false>,
                         cudaFuncAttributeMaxDynamicSharedMemorySize, SM_TOT);

    static cudaStream_t s2 = nullptr;
    static cudaEvent_t evFork, evJoin, evA1a, evA1b, evA2a, evA2b, evG4a, evSegA;
    if (s2 == nullptr) {
        cudaStreamCreateWithFlags(&s2, cudaStreamNonBlocking);
        cudaEventCreateWithFlags(&evFork, cudaEventDisableTiming);
        cudaEventCreateWithFlags(&evJoin, cudaEventDisableTiming);
        cudaEventCreateWithFlags(&evA1a, cudaEventDisableTiming);
        cudaEventCreateWithFlags(&evA1b, cudaEventDisableTiming);
        cudaEventCreateWithFlags(&evA2a, cudaEventDisableTiming);
        cudaEventCreateWithFlags(&evA2b, cudaEventDisableTiming);
        cudaEventCreateWithFlags(&evG4a, cudaEventDisableTiming);
        cudaEventCreateWithFlags(&evSegA, cudaEventDisableTiming);
    }

    const int gemm_blocks  = (NN + 127) / 128;             // 391 (3 waves)
    const int gemm_blkA    = SPLITR / 128;                 // 296 = 2 full waves
    const int gemm_blkB    = (NN - SPLITR + 127) / 128;    // 95  = 1 wave
    const int edge_blocks  = (EE + 255) / 256;
    const int aggA_blocks  = (SPLITR * 32 + 255) / 256;
    const int aggB_blocks  = ((NN - SPLITR) * 32 + 255) / 256;
    const int segA_blocks  = SPLITR / SEG_CH;              // 592 (aligned)
    const int segB_blocks  = (NN - SPLITR + SEG_CH - 1) / SEG_CH;

    // Main: W prep; fork CSR build + out zeroing to s2.
    // evJoin is recorded AFTER zero_out so everything downstream of evJoin
    // (including both seg_sum kernels) is ordered after the output zeroing.
    prep_w<<<256, 256>>>(W1, W2, W3, W4, wsp);
    cudaEventRecord(evFork, 0);
    cudaStreamWaitEvent(s2, evFork, 0);
    csr_zero<<<(NN + 255) / 256, 256, 0, s2>>>(cur);
    csr_hist<<<edge_blocks, 256, 0, s2>>>(ei, cur);
    csr_scan1<<<SCAN_B, 256, 0, s2>>>(cur, bsum);
    csr_scan2<<<1, 32, 0, s2>>>(bsum, rp);
    csr_scan3<<<SCAN_B, 256, 0, s2>>>(cur, bsum, rp, cur);
    csr_place<<<edge_blocks, 256, 0, s2>>>(ei, cur, ssrc);
    zero_out<<<(GG * HD + 255) / 256, 256, 0, s2>>>(out, GG * HD);
    cudaEventRecord(evJoin, s2);

    // Main: G1, G2 full-width (overlap CSR build).  x -> bufA -> bufB
    gemm_f16<true><<<gemm_blocks, 512, SM_TOT>>>(
        x, wsp + 0 * 32768, b1, g1, be1, mm1, mv1, bufA, 0, NN);
    gemm_f16<false><<<gemm_blocks, 512, SM_TOT>>>(
        bufA, wsp + 1 * 32768, b2, nullptr, nullptr, nullptr, nullptr,
        bufB, 0, NN);

    // agg1 (bufB -> bufC): part A on main, part B on s2 hidden under G3a.
    // bufB is read-only from here until agg2a writes it (after full G3).
    cudaStreamWaitEvent(0, evJoin, 0);
    csr_agg<<<aggA_blocks, 256>>>(bufB, rp, ssrc, bufC, 0, SPLITR);
    cudaEventRecord(evA1a, 0);
    cudaStreamWaitEvent(s2, evA1a, 0);
    csr_agg<<<aggB_blocks, 256, 0, s2>>>(bufB, rp, ssrc, bufC, SPLITR, NN);
    cudaEventRecord(evA1b, s2);

    // G3 (bufC -> bufA): 2-wave part A now; 1-wave part B after agg1b.
    gemm_f16<true><<<gemm_blkA, 512, SM_TOT>>>(
        bufC, wsp + 2 * 32768, b3, g2, be2, mm2, mv2, bufA, 0, NN);
    cudaStreamWaitEvent(0, evA1b, 0);
    gemm_f16<true><<<gemm_blkB, 512, SM_TOT>>>(
        bufC, wsp + 2 * 32768, b3, g2, be2, mm2, mv2, bufA, SPLITR, NN);

    // agg2 (bufA -> bufB): same pattern. bufA stays read-only afterwards
    // (G4 writes bufC, NOT bufA — that was the R11 race).
    csr_agg<<<aggA_blocks, 256>>>(bufA, rp, ssrc, bufB, 0, SPLITR);
    cudaEventRecord(evA2a, 0);
    cudaStreamWaitEvent(s2, evA2a, 0);
    csr_agg<<<aggB_blocks, 256, 0, s2>>>(bufA, rp, ssrc, bufB, SPLITR, NN);
    cudaEventRecord(evA2b, s2);

    // G4 (bufB -> bufC): part A now (reads only rows < SPLITR, written by
    // agg2a); seg_a on s2 under G4b; part B after agg2b; seg_b; join.
    gemm_f16<false><<<gemm_blkA, 512, SM_TOT>>>(
        bufB, wsp + 3 * 32768, b4, nullptr, nullptr, nullptr, nullptr,
        bufC, 0, NN);
    cudaEventRecord(evG4a, 0);
    cudaStreamWaitEvent(s2, evG4a, 0);
    seg_sum<<<segA_blocks, 128, 0, s2>>>(bufC, bat, out, 0, SPLITR);
    cudaEventRecord(evSegA, s2);

    cudaStreamWaitEvent(0, evA2b, 0);
    gemm_f16<false><<<gemm_blkB, 512, SM_TOT>>>(
        bufB, wsp + 3 * 32768, b4, nullptr, nullptr, nullptr, nullptr,
        bufC, SPLITR, NN);
    seg_sum<<<segB_blocks, 128>>>(bufC, bat, out, SPLITR, NN);
    cudaStreamWaitEvent(0, evSegA, 0);
}

// round 13
// speedup vs baseline: 1.1623x; 1.1623x over previous
#include <cuda_runtime.h>
#include <cuda_fp16.h>

#define NN 50000
#define HD 128
#define EE 640000
#define GG 128

typedef unsigned int u32;
typedef unsigned short u16;
typedef unsigned long long u64;

// Scratch buffers
__device__ float g_bufA[NN * HD];
__device__ float g_bufB[NN * HD];
__device__ float g_bufC[NN * HD];
// Pre-split W: [layer][hi/lo][16384 halves], swizzled smem image.
__device__ __align__(16) u16 g_wsp[4 * 2 * 16384];
// CSR-by-dst scratch
__device__ int g_rp[NN + 1];
__device__ int g_cur[NN];
__device__ int g_ssrc[EE];
__device__ int g_bsum[256];

#define SCAN_B 196

__device__ __forceinline__ u32 smem_u32(const void* p) {
    u32 a;
    asm("{ .reg .u64 t; cvta.to.shared.u64 t, %1; cvt.u32.u64 %0, t; }"
        : "=r"(a) : "l"(p));
    return a;
}
__device__ __forceinline__ void mma_f16(float* d, const u32* a, const u32* b) {
    asm("mma.sync.aligned.m16n8k16.row.col.f32.f16.f16.f32 "
        "{%0,%1,%2,%3}, {%4,%5,%6,%7}, {%8,%9}, {%0,%1,%2,%3};"
        : "+f"(d[0]), "+f"(d[1]), "+f"(d[2]), "+f"(d[3])
        : "r"(a[0]), "r"(a[1]), "r"(a[2]), "r"(a[3]), "r"(b[0]), "r"(b[1]));
}
__device__ __forceinline__ void ldsm4(u32* r, u32 addr) {
    asm volatile("ldmatrix.sync.aligned.m8n8.x4.shared.b16 {%0,%1,%2,%3}, [%4];"
                 : "=r"(r[0]), "=r"(r[1]), "=r"(r[2]), "=r"(r[3]) : "r"(addr));
}
__device__ __forceinline__ void cp16(u32 smem, const void* g) {
    asm volatile("cp.async.cg.shared.global [%0], [%1], 16;"
                 :: "r"(smem), "l"(g) : "memory");
}
__device__ __forceinline__ int swz_idx(int r, int kh) {
    return r * 32 + ((((kh >> 3) ^ ((r >> 1) & 3)) << 3) | (kh & 7));
}

// ---------------------------------------------------------------------------
// W prep: f16 hi/lo split, transposed [n][k], k-chunked, swizzled.
// ---------------------------------------------------------------------------
__global__ void prep_w(const float* __restrict__ W1, const float* __restrict__ W2,
                       const float* __restrict__ W3, const float* __restrict__ W4,
                       u16* __restrict__ out)
{
    int t = blockIdx.x * 256 + threadIdx.x;
    int layer = t >> 14, e = t & 16383;
    int k = e >> 7, n = e & 127;
    const float* W = layer == 0 ? W1 : layer == 1 ? W2 : layer == 2 ? W3 : W4;
    float v = W[k * HD + n];
    __half hi = __float2half_rn(v);
    __half lo = __float2half_rn(v - __half2float(hi));
    int ch = k >> 5, kh = k & 31;
    int idx = ch * 4096 + swz_idx(n, kh);
    int base = layer * 32768;
    out[base + idx]         = __half_as_ushort(hi);
    out[base + 16384 + idx] = __half_as_ushort(lo);
}

// ---------------------------------------------------------------------------
// CSR build
// ---------------------------------------------------------------------------
__global__ void csr_zero(int* __restrict__ cnt)
{
    int t = blockIdx.x * blockDim.x + threadIdx.x;
    if (t < NN) cnt[t] = 0;
}
__global__ void csr_hist(const int* __restrict__ ei, int* __restrict__ cnt)
{
    int e = blockIdx.x * blockDim.x + threadIdx.x;
    if (e < EE) atomicAdd(cnt + __ldg(ei + 2 * e + 1), 1);
}
__global__ void csr_scan1(const int* __restrict__ cnt, int* __restrict__ bsum)
{
    __shared__ int s[256];
    int t = threadIdx.x, i = blockIdx.x * 256 + t;
    s[t] = (i < NN) ? cnt[i] : 0;
    __syncthreads();
    for (int o = 128; o > 0; o >>= 1) {
        if (t < o) s[t] += s[t + o];
        __syncthreads();
    }
    if (t == 0) bsum[blockIdx.x] = s[0];
}
__global__ void csr_scan2(int* __restrict__ bsum, int* __restrict__ rp)
{
    if (threadIdx.x == 0) {
        int run = 0;
        for (int b = 0; b < SCAN_B; b++) {
            int v = bsum[b];
            bsum[b] = run;
            run += v;
        }
        rp[NN] = run;
    }
}
__global__ void csr_scan3(const int* __restrict__ cnt, const int* __restrict__ bsum,
                          int* __restrict__ rp, int* __restrict__ cur)
{
    __shared__ int s[256];
    int t = threadIdx.x, i = blockIdx.x * 256 + t;
    int c = (i < NN) ? cnt[i] : 0;
    s[t] = c;
    __syncthreads();
    for (int o = 1; o < 256; o <<= 1) {
        int v = (t >= o) ? s[t - o] : 0;
        __syncthreads();
        s[t] += v;
        __syncthreads();
    }
    if (i < NN) {
        int excl = bsum[blockIdx.x] + s[t] - c;
        rp[i] = excl;
        cur[i] = excl;
    }
}
__global__ void csr_place(const int* __restrict__ ei, int* __restrict__ cur,
                          int* __restrict__ ssrc)
{
    int e = blockIdx.x * blockDim.x + threadIdx.x;
    if (e >= EE) return;
    int src = __ldg(ei + 2 * e);
    int dst = __ldg(ei + 2 * e + 1);
    int pos = atomicAdd(cur + dst, 1);
    ssrc[pos] = src;
}

// ---------------------------------------------------------------------------
// Atomic-free aggregate: out[d,:] = h[d,:] + sum_{e in row d} h[ssrc[e],:]
// ---------------------------------------------------------------------------
__global__ void __launch_bounds__(256) csr_agg(
    const float* __restrict__ h, const int* __restrict__ rp,
    const int* __restrict__ ssrc, float* __restrict__ out)
{
    int d = (blockIdx.x * blockDim.x + threadIdx.x) >> 5;
    if (d >= NN) return;
    int lane = threadIdx.x & 31;
    float4 acc = __ldg((const float4*)(h + (size_t)d * HD) + lane);
    int e = __ldg(rp + d), e1 = __ldg(rp + d + 1);
    for (; e + 4 <= e1; e += 4) {
        int s0 = __ldg(ssrc + e + 0);
        int s1 = __ldg(ssrc + e + 1);
        int s2 = __ldg(ssrc + e + 2);
        int s3 = __ldg(ssrc + e + 3);
        float4 v0 = __ldg((const float4*)(h + (size_t)s0 * HD) + lane);
        float4 v1 = __ldg((const float4*)(h + (size_t)s1 * HD) + lane);
        float4 v2 = __ldg((const float4*)(h + (size_t)s2 * HD) + lane);
        float4 v3 = __ldg((const float4*)(h + (size_t)s3 * HD) + lane);
        acc.x += (v0.x + v1.x) + (v2.x + v3.x);
        acc.y += (v0.y + v1.y) + (v2.y + v3.y);
        acc.z += (v0.z + v1.z) + (v2.z + v3.z);
        acc.w += (v0.w + v1.w) + (v2.w + v3.w);
    }
    for (; e < e1; ++e) {
        int s = __ldg(ssrc + e);
        float4 v = __ldg((const float4*)(h + (size_t)s * HD) + lane);
        acc.x += v.x; acc.y += v.y; acc.z += v.z; acc.w += v.w;
    }
    *((float4*)(out + (size_t)d * HD) + lane) = acc;
}

// ---------------------------------------------------------------------------
// Smem layout (bytes). Full-K resident. After the mainloop, the W+A regions
// (1536..132608) are dead and are reused by the SEG epilogue as a 128x132
// fp32 staging tile + 128 batch ids.
// ---------------------------------------------------------------------------
#define SM_BB  0
#define SM_SC  512
#define SM_OF  1024
#define SM_W   1536
#define SM_A   (SM_W + 65536)
#define SM_TOT (SM_A + 65536)            // 132608 B -> 1 CTA/SM, 16 warps
#define RED_STRIDE 132
#define SM_BATCH (SM_W + 128 * RED_STRIDE * 4)   // 69120 (+512 <= SM_TOT)

// ---------------------------------------------------------------------------
// Split-f16 GEMM (3xF16): out[M,128] = epi(A@W + bias), epi = relu [*sc+of].
// SEG=true: instead of writing the result matrix, reduce it by graph id
// (batch, sorted) straight into gout via per-column boundary-flush atomics.
// ---------------------------------------------------------------------------
template <bool DO_BN, bool SEG>
__global__ void __launch_bounds__(512, 1) gemm_f16(
    const float* __restrict__ A, const u16* __restrict__ wsp,
    const float* __restrict__ bias, const float* __restrict__ gam,
    const float* __restrict__ bet, const float* __restrict__ mmean,
    const float* __restrict__ mvar, float* __restrict__ out,
    const int* __restrict__ batch, float* __restrict__ gout, int M)
{
    extern __shared__ char sm[];
    const u32 sb = smem_u32(sm);
    float* const bbp = (float*)(sm + SM_BB);
    float* const scp = (float*)(sm + SM_SC);
    float* const ofp = (float*)(sm + SM_OF);

    const int tid = threadIdx.x, wid = tid >> 5, lane = tid & 31;
    const int g = lane >> 2, q = lane & 3;
    const int wm = wid & 3, wn = wid >> 2;
    const int row0 = blockIdx.x * 128;

    if (tid < 128) {
        bbp[tid] = bias[tid];
        float s = 1.f, o = 0.f;
        if (DO_BN) {
            s = gam[tid] * rsqrtf(mvar[tid] + 1e-3f);
            o = bet[tid] - mmean[tid] * s;
        }
        scp[tid] = s;
        ofp[tid] = o;
    }

#pragma unroll
    for (int i = 0; i < 8; i++) {
        int idx = tid + i * 512;
        cp16(sb + SM_W + idx * 16, (const char*)wsp + idx * 16);
    }

    {
        const int j4 = lane * 4;
        const int ch = lane >> 3;
        const int kh = j4 & 31;
#pragma unroll
        for (int i = 0; i < 8; i++) {
            int r = wid * 8 + i;
            int grow = row0 + r;
            float4 v = make_float4(0.f, 0.f, 0.f, 0.f);
            if (grow < M)
                v = *(const float4*)(A + (size_t)grow * HD + j4);
            __half hx = __float2half_rn(v.x), hy = __float2half_rn(v.y),
                   hz = __float2half_rn(v.z), hw = __float2half_rn(v.w);
            union { u16 s[4]; u64 u; } hp, lp;
            hp.s[0] = __half_as_ushort(hx); hp.s[1] = __half_as_ushort(hy);
            hp.s[2] = __half_as_ushort(hz); hp.s[3] = __half_as_ushort(hw);
            lp.s[0] = __half_as_ushort(__float2half_rn(v.x - __half2float(hx)));
            lp.s[1] = __half_as_ushort(__float2half_rn(v.y - __half2float(hy)));
            lp.s[2] = __half_as_ushort(__float2half_rn(v.z - __half2float(hz)));
            lp.s[3] = __half_as_ushort(__float2half_rn(v.w - __half2float(hw)));
            int hidx = swz_idx(r, kh);
            *(u64*)(sm + SM_A + ch * 16384 + hidx * 2) = hp.u;
            *(u64*)(sm + SM_A + ch * 16384 + 8192 + hidx * 2) = lp.u;
        }
    }

    float d[2][4][4];
#pragma unroll
    for (int mt = 0; mt < 2; mt++)
#pragma unroll
        for (int nt = 0; nt < 4; nt++)
#pragma unroll
            for (int c = 0; c < 4; c++) d[mt][nt][c] = 0.f;

    asm volatile("cp.async.commit_group;" ::: "memory");
    asm volatile("cp.async.wait_group 0;" ::: "memory");
    __syncthreads();

#pragma unroll
    for (int ch = 0; ch < 4; ++ch) {
        const u32 abase = sb + SM_A + ch * 16384;
        const u32 wbase = sb + SM_W + ch * 8192;
#pragma unroll
        for (int s = 0; s < 2; ++s) {
            u32 fa_hi[2][4], fa_lo[2][4];
            const int ar = wm * 32 + (lane & 7) + ((lane & 8) ? 8 : 0);
            const int aj = s * 2 + ((lane & 16) ? 1 : 0);
#pragma unroll
            for (int mt = 0; mt < 2; mt++) {
                int r = ar + mt * 16;
                u32 off = (u32)(r * 64 + ((aj ^ ((r >> 1) & 3)) << 4));
                ldsm4(fa_hi[mt], abase + off);
                ldsm4(fa_lo[mt], abase + 8192 + off);
            }
            u32 fb_hi[4][2], fb_lo[4][2];
            const int brb = wn * 32 + ((lane & 16) ? 8 : 0) + (lane & 7);
            const int bj = s * 2 + ((lane & 8) ? 1 : 0);
#pragma unroll
            for (int t = 0; t < 2; t++) {
                int r = brb + t * 16;
                u32 off = (u32)(r * 64 + ((bj ^ ((r >> 1) & 3)) << 4));
                u32 tmp[4];
                ldsm4(tmp, wbase + off);
                fb_hi[2 * t][0] = tmp[0]; fb_hi[2 * t][1] = tmp[1];
                fb_hi[2 * t + 1][0] = tmp[2]; fb_hi[2 * t + 1][1] = tmp[3];
                ldsm4(tmp, wbase + 32768 + off);
                fb_lo[2 * t][0] = tmp[0]; fb_lo[2 * t][1] = tmp[1];
                fb_lo[2 * t + 1][0] = tmp[2]; fb_lo[2 * t + 1][1] = tmp[3];
            }
#pragma unroll
            for (int mt = 0; mt < 2; mt++)
#pragma unroll
                for (int nt = 0; nt < 4; nt++)
                    mma_f16(d[mt][nt], fa_hi[mt], fb_hi[nt]);
#pragma unroll
            for (int mt = 0; mt < 2; mt++)
#pragma unroll
                for (int nt = 0; nt < 4; nt++)
                    mma_f16(d[mt][nt], fa_hi[mt], fb_lo[nt]);
#pragma unroll
            for (int mt = 0; mt < 2; mt++)
#pragma unroll
                for (int nt = 0; nt < 4; nt++)
                    mma_f16(d[mt][nt], fa_lo[mt], fb_hi[nt]);
        }
    }

    const int q2 = q * 2;

    if (!SEG) {
#pragma unroll
        for (int mt = 0; mt < 2; mt++) {
            int r0 = row0 + wm * 32 + mt * 16 + g;
#pragma unroll
            for (int nt = 0; nt < 4; nt++) {
                int col = wn * 32 + nt * 8 + q2;
                float s0 = scp[col], s1 = scp[col + 1];
                float o0 = ofp[col], o1 = ofp[col + 1];
                float B0 = bbp[col], B1 = bbp[col + 1];
                float v0 = fmaxf(d[mt][nt][0] + B0, 0.f) * s0 + o0;
                float v1 = fmaxf(d[mt][nt][1] + B1, 0.f) * s1 + o1;
                float v2 = fmaxf(d[mt][nt][2] + B0, 0.f) * s0 + o0;
                float v3 = fmaxf(d[mt][nt][3] + B1, 0.f) * s1 + o1;
                if (r0 < M)
                    *(float2*)(out + (size_t)r0 * HD + col) = make_float2(v0, v1);
                if (r0 + 8 < M)
                    *(float2*)(out + (size_t)(r0 + 8) * HD + col) = make_float2(v2, v3);
            }
        }
    } else {
        // Fused segment-sum epilogue. Reuse dead W/A smem as a 128x132 fp32
        // staging tile (stride 132: column reads conflict-free).
        float* red = (float*)(sm + SM_W);
        int* bsm = (int*)(sm + SM_BATCH);
        __syncthreads();                 // mainloop smem reads done
#pragma unroll
        for (int mt = 0; mt < 2; mt++) {
            int lr = wm * 32 + mt * 16 + g;     // local row
            bool ok0 = (row0 + lr < M), ok1 = (row0 + lr + 8 < M);
#pragma unroll
            for (int nt = 0; nt < 4; nt++) {
                int col = wn * 32 + nt * 8 + q2;
                float B0 = bbp[col], B1 = bbp[col + 1];
                float v0 = ok0 ? fmaxf(d[mt][nt][0] + B0, 0.f) : 0.f;
                float v1 = ok0 ? fmaxf(d[mt][nt][1] + B1, 0.f) : 0.f;
                float v2 = ok1 ? fmaxf(d[mt][nt][2] + B0, 0.f) : 0.f;
                float v3 = ok1 ? fmaxf(d[mt][nt][3] + B1, 0.f) : 0.f;
                *(float2*)&red[lr * RED_STRIDE + col] = make_float2(v0, v1);
                *(float2*)&red[(lr + 8) * RED_STRIDE + col] = make_float2(v2, v3);
            }
        }
        if (tid < 128)
            bsm[tid] = (row0 + tid < M) ? __ldg(batch + row0 + tid) : -1;
        __syncthreads();
        // 512 threads: column c = tid&127, row chunk part = tid>>7 (32 rows).
        const int c = tid & 127, part = tid >> 7;
        const int rb = part * 32;
        float acc = 0.f;
        int curb = bsm[rb];
#pragma unroll
        for (int r = 0; r < 32; ++r) {
            int b = bsm[rb + r];
            if (b != curb) {
                if (curb >= 0) atomicAdd(gout + (size_t)curb * HD + c, acc);
                acc = 0.f;
                curb = b;
            }
            acc += red[(rb + r) * RED_STRIDE + c];
        }
        if (curb >= 0) atomicAdd(gout + (size_t)curb * HD + c, acc);
    }
}

__global__ void zero_out(float* __restrict__ out, int n)
{
    int t = blockIdx.x * blockDim.x + threadIdx.x;
    if (t < n) out[t] = 0.f;
}

extern "C" void kernel_launch(void* const* d_in, const int* in_sizes, int n_in,
                              void* d_out, int out_size)
{
    const float* x   = (const float*)d_in[0];
    const int*   ei  = (const int*)d_in[1];
    const int*   bat = (const int*)d_in[2];
    const float* W1  = (const float*)d_in[3];
    const float* b1  = (const float*)d_in[4];
    const float* g1  = (const float*)d_in[5];
    const float* be1 = (const float*)d_in[6];
    const float* mm1 = (const float*)d_in[7];
    const float* mv1 = (const float*)d_in[8];
    const float* W2  = (const float*)d_in[9];
    const float* b2  = (const float*)d_in[10];
    const float* W3  = (const float*)d_in[11];
    const float* b3  = (const float*)d_in[12];
    const float* g2  = (const float*)d_in[13];
    const float* be2 = (const float*)d_in[14];
    const float* mm2 = (const float*)d_in[15];
    const float* mv2 = (const float*)d_in[16];
    const float* W4  = (const float*)d_in[17];
    const float* b4  = (const float*)d_in[18];
    float* out = (float*)d_out;

    float *bufA, *bufB, *bufC;
    u16* wsp;
    int *rp, *cur, *ssrc, *bsum;
    cudaGetSymbolAddress((void**)&bufA, g_bufA);
    cudaGetSymbolAddress((void**)&bufB, g_bufB);
    cudaGetSymbolAddress((void**)&bufC, g_bufC);
    cudaGetSymbolAddress((void**)&wsp, g_wsp);
    cudaGetSymbolAddress((void**)&rp, g_rp);
    cudaGetSymbolAddress((void**)&cur, g_cur);
    cudaGetSymbolAddress((void**)&ssrc, g_ssrc);
    cudaGetSymbolAddress((void**)&bsum, g_bsum);

    cudaFuncSetAttribute(gemm_f16<true, false>,
                         cudaFuncAttributeMaxDynamicSharedMemorySize, SM_TOT);
    cudaFuncSetAttribute(gemm_f16<false, false>,
                         cudaFuncAttributeMaxDynamicSharedMemorySize, SM_TOT);
    cudaFuncSetAttribute(gemm_f16<false, true>,
                         cudaFuncAttributeMaxDynamicSharedMemorySize, SM_TOT);

    static cudaStream_t s2 = nullptr;
    static cudaEvent_t evFork = nullptr, evJoin = nullptr;
    if (s2 == nullptr) {
        cudaStreamCreateWithFlags(&s2, cudaStreamNonBlocking);
        cudaEventCreateWithFlags(&evFork, cudaEventDisableTiming);
        cudaEventCreateWithFlags(&evJoin, cudaEventDisableTiming);
    }

    const int gemm_blocks = (NN + 127) / 128;          // 391
    const int edge_blocks = (EE + 255) / 256;
    const int agg_blocks  = (NN * 32 + 255) / 256;

    // Main: W prep; fork CSR build + output zeroing to s2. evJoin recorded
    // AFTER zero_out so G4's fused atomics are ordered after the zeroing.
    prep_w<<<256, 256>>>(W1, W2, W3, W4, wsp);
    cudaEventRecord(evFork, 0);
    cudaStreamWaitEvent(s2, evFork, 0);
    csr_zero<<<(NN + 255) / 256, 256, 0, s2>>>(cur);
    csr_hist<<<edge_blocks, 256, 0, s2>>>(ei, cur);
    csr_scan1<<<SCAN_B, 256, 0, s2>>>(cur, bsum);
    csr_scan2<<<1, 32, 0, s2>>>(bsum, rp);
    csr_scan3<<<SCAN_B, 256, 0, s2>>>(cur, bsum, rp, cur);
    csr_place<<<edge_blocks, 256, 0, s2>>>(ei, cur, ssrc);
    zero_out<<<(GG * HD + 255) / 256, 256, 0, s2>>>(out, GG * HD);
    cudaEventRecord(evJoin, s2);

    // h = bn1(relu(x@W1+b1))            x -> bufA
    gemm_f16<true, false><<<gemm_blocks, 512, SM_TOT>>>(
        x, wsp + 0 * 32768, b1, g1, be1, mm1, mv1, bufA, nullptr, nullptr, NN);
    // h = relu(h@W2+b2)                 bufA -> bufB
    gemm_f16<false, false><<<gemm_blocks, 512, SM_TOT>>>(
        bufA, wsp + 1 * 32768, b2, nullptr, nullptr, nullptr, nullptr,
        bufB, nullptr, nullptr, NN);

    // Join: csr_agg needs the CSR arrays (and transitively zero_out is done).
    cudaStreamWaitEvent(0, evJoin, 0);

    // bufC = bufB + aggregate(bufB)
    csr_agg<<<agg_blocks, 256>>>(bufB, rp, ssrc, bufC);
    // h = bn2(relu(bufC@W3+b3))         bufC -> bufA
    gemm_f16<true, false><<<gemm_blocks, 512, SM_TOT>>>(
        bufC, wsp + 2 * 32768, b3, g2, be2, mm2, mv2, bufA, nullptr, nullptr, NN);
    // bufB = bufA + aggregate(bufA)
    csr_agg<<<agg_blocks, 256>>>(bufA, rp, ssrc, bufB);
    // out += segsum(relu(bufB@W4+b4))   fused epilogue, no matrix write
    gemm_f16<false, true><<<gemm_blocks, 512, SM_TOT>>>(
        bufB, wsp + 3 * 32768, b4, nullptr, nullptr, nullptr, nullptr,
        nullptr, bat, out, NN);
}

// round 14
// speedup vs baseline: 1.1634x; 1.0010x over previous
#include <cuda_runtime.h>
#include <cuda_fp16.h>

#define NN 50000
#define HD 128
#define EE 640000
#define GG 128

typedef unsigned int u32;
typedef unsigned short u16;
typedef unsigned long long u64;

// Scratch buffers
__device__ float g_bufA[NN * HD];
__device__ float g_bufB[NN * HD];
__device__ float g_bufC[NN * HD];
// Pre-split W: [layer][hi/lo][16384 halves], swizzled smem image.
__device__ __align__(16) u16 g_wsp[4 * 2 * 16384];
// CSR-by-dst scratch
__device__ int g_rp[NN + 1];
__device__ int g_cur[NN];
__device__ int g_ssrc[EE];
__device__ int g_bsum[256];

#define SCAN_B 196

__device__ __forceinline__ u32 smem_u32(const void* p) {
    u32 a;
    asm("{ .reg .u64 t; cvta.to.shared.u64 t, %1; cvt.u32.u64 %0, t; }"
        : "=r"(a) : "l"(p));
    return a;
}
__device__ __forceinline__ void mma_f16(float* d, const u32* a, const u32* b) {
    asm("mma.sync.aligned.m16n8k16.row.col.f32.f16.f16.f32 "
        "{%0,%1,%2,%3}, {%4,%5,%6,%7}, {%8,%9}, {%0,%1,%2,%3};"
        : "+f"(d[0]), "+f"(d[1]), "+f"(d[2]), "+f"(d[3])
        : "r"(a[0]), "r"(a[1]), "r"(a[2]), "r"(a[3]), "r"(b[0]), "r"(b[1]));
}
__device__ __forceinline__ void ldsm4(u32* r, u32 addr) {
    asm volatile("ldmatrix.sync.aligned.m8n8.x4.shared.b16 {%0,%1,%2,%3}, [%4];"
                 : "=r"(r[0]), "=r"(r[1]), "=r"(r[2]), "=r"(r[3]) : "r"(addr));
}
__device__ __forceinline__ void cp16(u32 smem, const void* g) {
    asm volatile("cp.async.cg.shared.global [%0], [%1], 16;"
                 :: "r"(smem), "l"(g) : "memory");
}
__device__ __forceinline__ int swz_idx(int r, int kh) {
    return r * 32 + ((((kh >> 3) ^ ((r >> 1) & 3)) << 3) | (kh & 7));
}
// Pack two fp32 into (hi half2, lo half2) u32s.
__device__ __forceinline__ void pack_hilo(float v0, float v1, u32& hp, u32& lp) {
    __half h0 = __float2half_rn(v0), h1 = __float2half_rn(v1);
    __half l0 = __float2half_rn(v0 - __half2float(h0));
    __half l1 = __float2half_rn(v1 - __half2float(h1));
    hp = (u32)__half_as_ushort(h0) | ((u32)__half_as_ushort(h1) << 16);
    lp = (u32)__half_as_ushort(l0) | ((u32)__half_as_ushort(l1) << 16);
}

// ---------------------------------------------------------------------------
// W prep: f16 hi/lo split, transposed [n][k], k-chunked, swizzled.
// ---------------------------------------------------------------------------
__global__ void prep_w(const float* __restrict__ W1, const float* __restrict__ W2,
                       const float* __restrict__ W3, const float* __restrict__ W4,
                       u16* __restrict__ out)
{
    int t = blockIdx.x * 256 + threadIdx.x;
    int layer = t >> 14, e = t & 16383;
    int k = e >> 7, n = e & 127;
    const float* W = layer == 0 ? W1 : layer == 1 ? W2 : layer == 2 ? W3 : W4;
    float v = W[k * HD + n];
    __half hi = __float2half_rn(v);
    __half lo = __float2half_rn(v - __half2float(hi));
    int ch = k >> 5, kh = k & 31;
    int idx = ch * 4096 + swz_idx(n, kh);
    int base = layer * 32768;
    out[base + idx]         = __half_as_ushort(hi);
    out[base + 16384 + idx] = __half_as_ushort(lo);
}

// ---------------------------------------------------------------------------
// CSR build
// ---------------------------------------------------------------------------
__global__ void csr_zero(int* __restrict__ cnt)
{
    int t = blockIdx.x * blockDim.x + threadIdx.x;
    if (t < NN) cnt[t] = 0;
}
__global__ void csr_hist(const int* __restrict__ ei, int* __restrict__ cnt)
{
    int e = blockIdx.x * blockDim.x + threadIdx.x;
    if (e < EE) atomicAdd(cnt + __ldg(ei + 2 * e + 1), 1);
}
__global__ void csr_scan1(const int* __restrict__ cnt, int* __restrict__ bsum)
{
    __shared__ int s[256];
    int t = threadIdx.x, i = blockIdx.x * 256 + t;
    s[t] = (i < NN) ? cnt[i] : 0;
    __syncthreads();
    for (int o = 128; o > 0; o >>= 1) {
        if (t < o) s[t] += s[t + o];
        __syncthreads();
    }
    if (t == 0) bsum[blockIdx.x] = s[0];
}
__global__ void csr_scan2(int* __restrict__ bsum, int* __restrict__ rp)
{
    if (threadIdx.x == 0) {
        int run = 0;
        for (int b = 0; b < SCAN_B; b++) {
            int v = bsum[b];
            bsum[b] = run;
            run += v;
        }
        rp[NN] = run;
    }
}
__global__ void csr_scan3(const int* __restrict__ cnt, const int* __restrict__ bsum,
                          int* __restrict__ rp, int* __restrict__ cur)
{
    __shared__ int s[256];
    int t = threadIdx.x, i = blockIdx.x * 256 + t;
    int c = (i < NN) ? cnt[i] : 0;
    s[t] = c;
    __syncthreads();
    for (int o = 1; o < 256; o <<= 1) {
        int v = (t >= o) ? s[t - o] : 0;
        __syncthreads();
        s[t] += v;
        __syncthreads();
    }
    if (i < NN) {
        int excl = bsum[blockIdx.x] + s[t] - c;
        rp[i] = excl;
        cur[i] = excl;
    }
}
__global__ void csr_place(const int* __restrict__ ei, int* __restrict__ cur,
                          int* __restrict__ ssrc)
{
    int e = blockIdx.x * blockDim.x + threadIdx.x;
    if (e >= EE) return;
    int src = __ldg(ei + 2 * e);
    int dst = __ldg(ei + 2 * e + 1);
    int pos = atomicAdd(cur + dst, 1);
    ssrc[pos] = src;
}

// ---------------------------------------------------------------------------
// Atomic-free aggregate: out[d,:] = h[d,:] + sum_{e in row d} h[ssrc[e],:]
// ---------------------------------------------------------------------------
__global__ void __launch_bounds__(256) csr_agg(
    const float* __restrict__ h, const int* __restrict__ rp,
    const int* __restrict__ ssrc, float* __restrict__ out)
{
    int d = (blockIdx.x * blockDim.x + threadIdx.x) >> 5;
    if (d >= NN) return;
    int lane = threadIdx.x & 31;
    float4 acc = __ldg((const float4*)(h + (size_t)d * HD) + lane);
    int e = __ldg(rp + d), e1 = __ldg(rp + d + 1);
    for (; e + 4 <= e1; e += 4) {
        int s0 = __ldg(ssrc + e + 0);
        int s1 = __ldg(ssrc + e + 1);
        int s2 = __ldg(ssrc + e + 2);
        int s3 = __ldg(ssrc + e + 3);
        float4 v0 = __ldg((const float4*)(h + (size_t)s0 * HD) + lane);
        float4 v1 = __ldg((const float4*)(h + (size_t)s1 * HD) + lane);
        float4 v2 = __ldg((const float4*)(h + (size_t)s2 * HD) + lane);
        float4 v3 = __ldg((const float4*)(h + (size_t)s3 * HD) + lane);
        acc.x += (v0.x + v1.x) + (v2.x + v3.x);
        acc.y += (v0.y + v1.y) + (v2.y + v3.y);
        acc.z += (v0.z + v1.z) + (v2.z + v3.z);
        acc.w += (v0.w + v1.w) + (v2.w + v3.w);
    }
    for (; e < e1; ++e) {
        int s = __ldg(ssrc + e);
        float4 v = __ldg((const float4*)(h + (size_t)s * HD) + lane);
        acc.x += v.x; acc.y += v.y; acc.z += v.z; acc.w += v.w;
    }
    *((float4*)(out + (size_t)d * HD) + lane) = acc;
}

// ---------------------------------------------------------------------------
// Single-GEMM smem layout (G3, G4+seg).
// ---------------------------------------------------------------------------
#define SM_BB  0
#define SM_SC  512
#define SM_OF  1024
#define SM_W   1536
#define SM_A   (SM_W + 65536)
#define SM_TOT (SM_A + 65536)            // 132608 B
#define RED_STRIDE 132
#define SM_BATCH (SM_W + 128 * RED_STRIDE * 4)   // 69120 (+512 <= SM_TOT)

// Fused G1+G2 layout.
#define F_BB1 0
#define F_SC  512
#define F_OF  1024
#define F_BB2 1536
#define F_W1  2048
#define F_W2  (F_W1 + 65536)
#define F_A   (F_W2 + 65536)
#define F_TOT (F_A + 65536)              // 198656 B

// Shared mainloop: runs 8 k16-steps of 3xF16 MMA, A at abase0, W at wbase0.
#define MAINLOOP(d, sb, abase0, wbase0)                                       \
    _Pragma("unroll")                                                         \
    for (int ch = 0; ch < 4; ++ch) {                                          \
        const u32 abase = (abase0) + ch * 16384;                              \
        const u32 wbase = (wbase0) + ch * 8192;                               \
        _Pragma("unroll")                                                     \
        for (int s = 0; s < 2; ++s) {                                         \
            u32 fa_hi[2][4], fa_lo[2][4];                                     \
            const int ar = wm * 32 + (lane & 7) + ((lane & 8) ? 8 : 0);       \
            const int aj = s * 2 + ((lane & 16) ? 1 : 0);                     \
            _Pragma("unroll")                                                 \
            for (int mt = 0; mt < 2; mt++) {                                  \
                int r = ar + mt * 16;                                         \
                u32 off = (u32)(r * 64 + ((aj ^ ((r >> 1) & 3)) << 4));       \
                ldsm4(fa_hi[mt], abase + off);                                \
                ldsm4(fa_lo[mt], abase + 8192 + off);                         \
            }                                                                 \
            u32 fb_hi[4][2], fb_lo[4][2];                                     \
            const int brb = wn * 32 + ((lane & 16) ? 8 : 0) + (lane & 7);     \
            const int bj = s * 2 + ((lane & 8) ? 1 : 0);                      \
            _Pragma("unroll")                                                 \
            for (int t = 0; t < 2; t++) {                                     \
                int r = brb + t * 16;                                         \
                u32 off = (u32)(r * 64 + ((bj ^ ((r >> 1) & 3)) << 4));       \
                u32 tmp[4];                                                   \
                ldsm4(tmp, wbase + off);                                      \
                fb_hi[2 * t][0] = tmp[0]; fb_hi[2 * t][1] = tmp[1];           \
                fb_hi[2 * t + 1][0] = tmp[2]; fb_hi[2 * t + 1][1] = tmp[3];   \
                ldsm4(tmp, wbase + 32768 + off);                              \
                fb_lo[2 * t][0] = tmp[0]; fb_lo[2 * t][1] = tmp[1];           \
                fb_lo[2 * t + 1][0] = tmp[2]; fb_lo[2 * t + 1][1] = tmp[3];   \
            }                                                                 \
            _Pragma("unroll")                                                 \
            for (int mt = 0; mt < 2; mt++)                                    \
                _Pragma("unroll")                                             \
                for (int nt = 0; nt < 4; nt++)                                \
                    mma_f16(d[mt][nt], fa_hi[mt], fb_hi[nt]);                 \
            _Pragma("unroll")                                                 \
            for (int mt = 0; mt < 2; mt++)                                    \
                _Pragma("unroll")                                             \
                for (int nt = 0; nt < 4; nt++)                                \
                    mma_f16(d[mt][nt], fa_hi[mt], fb_lo[nt]);                 \
            _Pragma("unroll")                                                 \
            for (int mt = 0; mt < 2; mt++)                                    \
                _Pragma("unroll")                                             \
                for (int nt = 0; nt < 4; nt++)                                \
                    mma_f16(d[mt][nt], fa_lo[mt], fb_hi[nt]);                 \
        }                                                                     \
    }

// ---------------------------------------------------------------------------
// Fused layers 1+2: out = relu(bn1(relu(x@W1+b1))@W2+b2).
// Phase 1 result is re-staged (f16 hi/lo, swizzled) into the dead A tile.
// ---------------------------------------------------------------------------
__global__ void __launch_bounds__(512, 1) gemm12(
    const float* __restrict__ A, const u16* __restrict__ w1sp,
    const u16* __restrict__ w2sp,
    const float* __restrict__ b1, const float* __restrict__ gam,
    const float* __restrict__ bet, const float* __restrict__ mmean,
    const float* __restrict__ mvar, const float* __restrict__ b2,
    float* __restrict__ out, int M)
{
    extern __shared__ char sm[];
    const u32 sb = smem_u32(sm);
    float* const bb1 = (float*)(sm + F_BB1);
    float* const scp = (float*)(sm + F_SC);
    float* const ofp = (float*)(sm + F_OF);
    float* const bb2 = (float*)(sm + F_BB2);

    const int tid = threadIdx.x, wid = tid >> 5, lane = tid & 31;
    const int g = lane >> 2, q = lane & 3;
    const int wm = wid & 3, wn = wid >> 2;
    const int row0 = blockIdx.x * 128;

    if (tid < 128) {
        bb1[tid] = b1[tid];
        float s = gam[tid] * rsqrtf(mvar[tid] + 1e-3f);
        scp[tid] = s;
        ofp[tid] = bet[tid] - mmean[tid] * s;
        bb2[tid] = b2[tid];
    }
    // W1 + W2 (128KB) via cp.async.
#pragma unroll
    for (int i = 0; i < 8; i++) {
        int idx = tid + i * 512;
        cp16(sb + F_W1 + idx * 16, (const char*)w1sp + idx * 16);
        cp16(sb + F_W2 + idx * 16, (const char*)w2sp + idx * 16);
    }
    // Stage x.
    {
        const int j4 = lane * 4;
        const int ch = lane >> 3;
        const int kh = j4 & 31;
#pragma unroll
        for (int i = 0; i < 8; i++) {
            int r = wid * 8 + i;
            int grow = row0 + r;
            float4 v = make_float4(0.f, 0.f, 0.f, 0.f);
            if (grow < M)
                v = *(const float4*)(A + (size_t)grow * HD + j4);
            u32 h0, l0, h1, l1;
            pack_hilo(v.x, v.y, h0, l0);
            pack_hilo(v.z, v.w, h1, l1);
            int hidx = swz_idx(r, kh);
            *(u32*)(sm + F_A + ch * 16384 + hidx * 2) = h0;
            *(u32*)(sm + F_A + ch * 16384 + hidx * 2 + 4) = h1;
            *(u32*)(sm + F_A + ch * 16384 + 8192 + hidx * 2) = l0;
            *(u32*)(sm + F_A + ch * 16384 + 8192 + hidx * 2 + 4) = l1;
        }
    }

    float d[2][4][4];
#pragma unroll
    for (int mt = 0; mt < 2; mt++)
#pragma unroll
        for (int nt = 0; nt < 4; nt++)
#pragma unroll
            for (int c = 0; c < 4; c++) d[mt][nt][c] = 0.f;

    asm volatile("cp.async.commit_group;" ::: "memory");
    asm volatile("cp.async.wait_group 0;" ::: "memory");
    __syncthreads();

    MAINLOOP(d, sb, sb + F_A, sb + F_W1);

    // Mid-epilogue: bn1(relu(.+b1)) -> f16 hi/lo restage into A tile.
    __syncthreads();                     // phase-1 A reads complete
    const int q2 = q * 2;
#pragma unroll
    for (int mt = 0; mt < 2; mt++) {
        int lr = wm * 32 + mt * 16 + g;
#pragma unroll
        for (int nt = 0; nt < 4; nt++) {
            int col = wn * 32 + nt * 8 + q2;
            float s0 = scp[col], s1 = scp[col + 1];
            float o0 = ofp[col], o1 = ofp[col + 1];
            float B0 = bb1[col], B1 = bb1[col + 1];
            float v0 = fmaxf(d[mt][nt][0] + B0, 0.f) * s0 + o0;
            float v1 = fmaxf(d[mt][nt][1] + B1, 0.f) * s1 + o1;
            float v2 = fmaxf(d[mt][nt][2] + B0, 0.f) * s0 + o0;
            float v3 = fmaxf(d[mt][nt][3] + B1, 0.f) * s1 + o1;
            int ch = col >> 5, kh = col & 31;
            u32 hp, lp;
            pack_hilo(v0, v1, hp, lp);
            int hidx = swz_idx(lr, kh);
            *(u32*)(sm + F_A + ch * 16384 + hidx * 2) = hp;
            *(u32*)(sm + F_A + ch * 16384 + 8192 + hidx * 2) = lp;
            pack_hilo(v2, v3, hp, lp);
            hidx = swz_idx(lr + 8, kh);
            *(u32*)(sm + F_A + ch * 16384 + hidx * 2) = hp;
            *(u32*)(sm + F_A + ch * 16384 + 8192 + hidx * 2) = lp;
        }
    }
#pragma unroll
    for (int mt = 0; mt < 2; mt++)
#pragma unroll
        for (int nt = 0; nt < 4; nt++)
#pragma unroll
            for (int c = 0; c < 4; c++) d[mt][nt][c] = 0.f;
    __syncthreads();

    MAINLOOP(d, sb, sb + F_A, sb + F_W2);

    // Final epilogue: relu(.+b2) -> out.
#pragma unroll
    for (int mt = 0; mt < 2; mt++) {
        int r0 = row0 + wm * 32 + mt * 16 + g;
#pragma unroll
        for (int nt = 0; nt < 4; nt++) {
            int col = wn * 32 + nt * 8 + q2;
            float B0 = bb2[col], B1 = bb2[col + 1];
            float v0 = fmaxf(d[mt][nt][0] + B0, 0.f);
            float v1 = fmaxf(d[mt][nt][1] + B1, 0.f);
            float v2 = fmaxf(d[mt][nt][2] + B0, 0.f);
            float v3 = fmaxf(d[mt][nt][3] + B1, 0.f);
            if (r0 < M)
                *(float2*)(out + (size_t)r0 * HD + col) = make_float2(v0, v1);
            if (r0 + 8 < M)
                *(float2*)(out + (size_t)(r0 + 8) * HD + col) = make_float2(v2, v3);
        }
    }
}

// ---------------------------------------------------------------------------
// Single split-f16 GEMM: out = epi(A@W + bias). SEG=true fuses the graph
// readout (sorted batch) into the epilogue via boundary-flush atomics.
// ---------------------------------------------------------------------------
template <bool DO_BN, bool SEG>
__global__ void __launch_bounds__(512, 1) gemm_f16(
    const float* __restrict__ A, const u16* __restrict__ wsp,
    const float* __restrict__ bias, const float* __restrict__ gam,
    const float* __restrict__ bet, const float* __restrict__ mmean,
    const float* __restrict__ mvar, float* __restrict__ out,
    const int* __restrict__ batch, float* __restrict__ gout, int M)
{
    extern __shared__ char sm[];
    const u32 sb = smem_u32(sm);
    float* const bbp = (float*)(sm + SM_BB);
    float* const scp = (float*)(sm + SM_SC);
    float* const ofp = (float*)(sm + SM_OF);

    const int tid = threadIdx.x, wid = tid >> 5, lane = tid & 31;
    const int g = lane >> 2, q = lane & 3;
    const int wm = wid & 3, wn = wid >> 2;
    const int row0 = blockIdx.x * 128;

    if (tid < 128) {
        bbp[tid] = bias[tid];
        float s = 1.f, o = 0.f;
        if (DO_BN) {
            s = gam[tid] * rsqrtf(mvar[tid] + 1e-3f);
            o = bet[tid] - mmean[tid] * s;
        }
        scp[tid] = s;
        ofp[tid] = o;
    }
#pragma unroll
    for (int i = 0; i < 8; i++) {
        int idx = tid + i * 512;
        cp16(sb + SM_W + idx * 16, (const char*)wsp + idx * 16);
    }
    {
        const int j4 = lane * 4;
        const int ch = lane >> 3;
        const int kh = j4 & 31;
#pragma unroll
        for (int i = 0; i < 8; i++) {
            int r = wid * 8 + i;
            int grow = row0 + r;
            float4 v = make_float4(0.f, 0.f, 0.f, 0.f);
            if (grow < M)
                v = *(const float4*)(A + (size_t)grow * HD + j4);
            u32 h0, l0, h1, l1;
            pack_hilo(v.x, v.y, h0, l0);
            pack_hilo(v.z, v.w, h1, l1);
            int hidx = swz_idx(r, kh);
            *(u32*)(sm + SM_A + ch * 16384 + hidx * 2) = h0;
            *(u32*)(sm + SM_A + ch * 16384 + hidx * 2 + 4) = h1;
            *(u32*)(sm + SM_A + ch * 16384 + 8192 + hidx * 2) = l0;
            *(u32*)(sm + SM_A + ch * 16384 + 8192 + hidx * 2 + 4) = l1;
        }
    }

    float d[2][4][4];
#pragma unroll
    for (int mt = 0; mt < 2; mt++)
#pragma unroll
        for (int nt = 0; nt < 4; nt++)
#pragma unroll
            for (int c = 0; c < 4; c++) d[mt][nt][c] = 0.f;

    asm volatile("cp.async.commit_group;" ::: "memory");
    asm volatile("cp.async.wait_group 0;" ::: "memory");
    __syncthreads();

    MAINLOOP(d, sb, sb + SM_A, sb + SM_W);

    const int q2 = q * 2;

    if (!SEG) {
#pragma unroll
        for (int mt = 0; mt < 2; mt++) {
            int r0 = row0 + wm * 32 + mt * 16 + g;
#pragma unroll
            for (int nt = 0; nt < 4; nt++) {
                int col = wn * 32 + nt * 8 + q2;
                float s0 = scp[col], s1 = scp[col + 1];
                float o0 = ofp[col], o1 = ofp[col + 1];
                float B0 = bbp[col], B1 = bbp[col + 1];
                float v0 = fmaxf(d[mt][nt][0] + B0, 0.f) * s0 + o0;
                float v1 = fmaxf(d[mt][nt][1] + B1, 0.f) * s1 + o1;
                float v2 = fmaxf(d[mt][nt][2] + B0, 0.f) * s0 + o0;
                float v3 = fmaxf(d[mt][nt][3] + B1, 0.f) * s1 + o1;
                if (r0 < M)
                    *(float2*)(out + (size_t)r0 * HD + col) = make_float2(v0, v1);
                if (r0 + 8 < M)
                    *(float2*)(out + (size_t)(r0 + 8) * HD + col) = make_float2(v2, v3);
            }
        }
    } else {
        float* red = (float*)(sm + SM_W);
        int* bsm = (int*)(sm + SM_BATCH);
        __syncthreads();
#pragma unroll
        for (int mt = 0; mt < 2; mt++) {
            int lr = wm * 32 + mt * 16 + g;
            bool ok0 = (row0 + lr < M), ok1 = (row0 + lr + 8 < M);
#pragma unroll
            for (int nt = 0; nt < 4; nt++) {
                int col = wn * 32 + nt * 8 + q2;
                float B0 = bbp[col], B1 = bbp[col + 1];
                float v0 = ok0 ? fmaxf(d[mt][nt][0] + B0, 0.f) : 0.f;
                float v1 = ok0 ? fmaxf(d[mt][nt][1] + B1, 0.f) : 0.f;
                float v2 = ok1 ? fmaxf(d[mt][nt][2] + B0, 0.f) : 0.f;
                float v3 = ok1 ? fmaxf(d[mt][nt][3] + B1, 0.f) : 0.f;
                *(float2*)&red[lr * RED_STRIDE + col] = make_float2(v0, v1);
                *(float2*)&red[(lr + 8) * RED_STRIDE + col] = make_float2(v2, v3);
            }
        }
        if (tid < 128)
            bsm[tid] = (row0 + tid < M) ? __ldg(batch + row0 + tid) : -1;
        __syncthreads();
        const int c = tid & 127, part = tid >> 7;
        const int rb = part * 32;
        float acc = 0.f;
        int curb = bsm[rb];
#pragma unroll
        for (int r = 0; r < 32; ++r) {
            int b = bsm[rb + r];
            if (b != curb) {
                if (curb >= 0) atomicAdd(gout + (size_t)curb * HD + c, acc);
                acc = 0.f;
                curb = b;
            }
            acc += red[(rb + r) * RED_STRIDE + c];
        }
        if (curb >= 0) atomicAdd(gout + (size_t)curb * HD + c, acc);
    }
}

__global__ void zero_out(float* __restrict__ out, int n)
{
    int t = blockIdx.x * blockDim.x + threadIdx.x;
    if (t < n) out[t] = 0.f;
}

extern "C" void kernel_launch(void* const* d_in, const int* in_sizes, int n_in,
                              void* d_out, int out_size)
{
    const float* x   = (const float*)d_in[0];
    const int*   ei  = (const int*)d_in[1];
    const int*   bat = (const int*)d_in[2];
    const float* W1  = (const float*)d_in[3];
    const float* b1  = (const float*)d_in[4];
    const float* g1  = (const float*)d_in[5];
    const float* be1 = (const float*)d_in[6];
    const float* mm1 = (const float*)d_in[7];
    const float* mv1 = (const float*)d_in[8];
    const float* W2  = (const float*)d_in[9];
    const float* b2  = (const float*)d_in[10];
    const float* W3  = (const float*)d_in[11];
    const float* b3  = (const float*)d_in[12];
    const float* g2  = (const float*)d_in[13];
    const float* be2 = (const float*)d_in[14];
    const float* mm2 = (const float*)d_in[15];
    const float* mv2 = (const float*)d_in[16];
    const float* W4  = (const float*)d_in[17];
    const float* b4  = (const float*)d_in[18];
    float* out = (float*)d_out;

    float *bufA, *bufB, *bufC;
    u16* wsp;
    int *rp, *cur, *ssrc, *bsum;
    cudaGetSymbolAddress((void**)&bufA, g_bufA);
    cudaGetSymbolAddress((void**)&bufB, g_bufB);
    cudaGetSymbolAddress((void**)&bufC, g_bufC);
    cudaGetSymbolAddress((void**)&wsp, g_wsp);
    cudaGetSymbolAddress((void**)&rp, g_rp);
    cudaGetSymbolAddress((void**)&cur, g_cur);
    cudaGetSymbolAddress((void**)&ssrc, g_ssrc);
    cudaGetSymbolAddress((void**)&bsum, g_bsum);

    cudaFuncSetAttribute(gemm12,
                         cudaFuncAttributeMaxDynamicSharedMemorySize, F_TOT);
    cudaFuncSetAttribute(gemm_f16<true, false>,
                         cudaFuncAttributeMaxDynamicSharedMemorySize, SM_TOT);
    cudaFuncSetAttribute(gemm_f16<false, true>,
                         cudaFuncAttributeMaxDynamicSharedMemorySize, SM_TOT);

    static cudaStream_t s2 = nullptr;
    static cudaEvent_t evFork = nullptr, evJoin = nullptr;
    if (s2 == nullptr) {
        cudaStreamCreateWithFlags(&s2, cudaStreamNonBlocking);
        cudaEventCreateWithFlags(&evFork, cudaEventDisableTiming);
        cudaEventCreateWithFlags(&evJoin, cudaEventDisableTiming);
    }

    const int gemm_blocks = (NN + 127) / 128;          // 391
    const int edge_blocks = (EE + 255) / 256;
    const int agg_blocks  = (NN * 32 + 255) / 256;

    // Main: W prep; fork CSR build + output zeroing to s2 (evJoin AFTER
    // zero_out so G4's fused atomics are ordered after the zeroing).
    prep_w<<<256, 256>>>(W1, W2, W3, W4, wsp);
    cudaEventRecord(evFork, 0);
    cudaStreamWaitEvent(s2, evFork, 0);
    csr_zero<<<(NN + 255) / 256, 256, 0, s2>>>(cur);
    csr_hist<<<edge_blocks, 256, 0, s2>>>(ei, cur);
    csr_scan1<<<SCAN_B, 256, 0, s2>>>(cur, bsum);
    csr_scan2<<<1, 32, 0, s2>>>(bsum, rp);
    csr_scan3<<<SCAN_B, 256, 0, s2>>>(cur, bsum, rp, cur);
    csr_place<<<edge_blocks, 256, 0, s2>>>(ei, cur, ssrc);
    zero_out<<<(GG * HD + 255) / 256, 256, 0, s2>>>(out, GG * HD);
    cudaEventRecord(evJoin, s2);

    // Fused layers 1+2: x -> bufB (overlaps CSR build).
    gemm12<<<gemm_blocks, 512, F_TOT>>>(
        x, wsp + 0 * 32768, wsp + 1 * 32768,
        b1, g1, be1, mm1, mv1, b2, bufB, NN);

    // Join: csr_agg needs the CSR arrays (and transitively zero_out done).
    cudaStreamWaitEvent(0, evJoin, 0);

    // bufC = bufB + aggregate(bufB)
    csr_agg<<<agg_blocks, 256>>>(bufB, rp, ssrc, bufC);
    // h = bn2(relu(bufC@W3+b3))  bufC -> bufA
    gemm_f16<true, false><<<gemm_blocks, 512, SM_TOT>>>(
        bufC, wsp + 2 * 32768, b3, g2, be2, mm2, mv2, bufA, nullptr, nullptr, NN);
    // bufB = bufA + aggregate(bufA)
    csr_agg<<<agg_blocks, 256>>>(bufA, rp, ssrc, bufB);
    // out += segsum(relu(bufB@W4+b4))  fused epilogue
    gemm_f16<false, true><<<gemm_blocks, 512, SM_TOT>>>(
        bufB, wsp + 3 * 32768, b4, nullptr, nullptr, nullptr, nullptr,
        nullptr, bat, out, NN);
}

// round 15
// speedup vs baseline: 1.4091x; 1.2112x over previous
#include <cuda_runtime.h>
#include <cuda_fp16.h>

#define NN 50000
#define HD 128
#define EE 640000
#define GG 128

typedef unsigned int u32;
typedef unsigned short u16;
typedef unsigned long long u64;

// Scratch buffers
__device__ float g_bufA[NN * HD];
__device__ float g_bufB[NN * HD];
__device__ float g_bufC[NN * HD];
// Pre-converted W: [layer][16384 halves] (f16, transposed, swizzled image).
__device__ __align__(16) u16 g_wsp[4 * 16384];
// CSR-by-dst scratch
__device__ int g_rp[NN + 1];
__device__ int g_cur[NN];
__device__ int g_ssrc[EE];
__device__ int g_bsum[256];

#define SCAN_B 196

__device__ __forceinline__ u32 smem_u32(const void* p) {
    u32 a;
    asm("{ .reg .u64 t; cvta.to.shared.u64 t, %1; cvt.u32.u64 %0, t; }"
        : "=r"(a) : "l"(p));
    return a;
}
__device__ __forceinline__ void mma_f16(float* d, const u32* a, const u32* b) {
    asm("mma.sync.aligned.m16n8k16.row.col.f32.f16.f16.f32 "
        "{%0,%1,%2,%3}, {%4,%5,%6,%7}, {%8,%9}, {%0,%1,%2,%3};"
        : "+f"(d[0]), "+f"(d[1]), "+f"(d[2]), "+f"(d[3])
        : "r"(a[0]), "r"(a[1]), "r"(a[2]), "r"(a[3]), "r"(b[0]), "r"(b[1]));
}
__device__ __forceinline__ void ldsm4(u32* r, u32 addr) {
    asm volatile("ldmatrix.sync.aligned.m8n8.x4.shared.b16 {%0,%1,%2,%3}, [%4];"
                 : "=r"(r[0]), "=r"(r[1]), "=r"(r[2]), "=r"(r[3]) : "r"(addr));
}
__device__ __forceinline__ void cp16(u32 smem, const void* g) {
    asm volatile("cp.async.cg.shared.global [%0], [%1], 16;"
                 :: "r"(smem), "l"(g) : "memory");
}
__device__ __forceinline__ int swz_idx(int r, int kh) {
    return r * 32 + ((((kh >> 3) ^ ((r >> 1) & 3)) << 3) | (kh & 7));
}
// Pack two fp32 into one half2 u32.
__device__ __forceinline__ u32 pack_h2(float v0, float v1) {
    __half h0 = __float2half_rn(v0), h1 = __float2half_rn(v1);
    return (u32)__half_as_ushort(h0) | ((u32)__half_as_ushort(h1) << 16);
}

// ---------------------------------------------------------------------------
// W prep: f16 convert, transposed [n][k], k-chunked (4x32), swizzled.
// ---------------------------------------------------------------------------
__global__ void prep_w(const float* __restrict__ W1, const float* __restrict__ W2,
                       const float* __restrict__ W3, const float* __restrict__ W4,
                       u16* __restrict__ out)
{
    int t = blockIdx.x * 256 + threadIdx.x;
    int layer = t >> 14, e = t & 16383;
    int k = e >> 7, n = e & 127;
    const float* W = layer == 0 ? W1 : layer == 1 ? W2 : layer == 2 ? W3 : W4;
    float v = W[k * HD + n];
    int ch = k >> 5, kh = k & 31;
    out[layer * 16384 + ch * 4096 + swz_idx(n, kh)] =
        __half_as_ushort(__float2half_rn(v));
}

// ---------------------------------------------------------------------------
// CSR build
// ---------------------------------------------------------------------------
__global__ void csr_zero(int* __restrict__ cnt)
{
    int t = blockIdx.x * blockDim.x + threadIdx.x;
    if (t < NN) cnt[t] = 0;
}
__global__ void csr_hist(const int* __restrict__ ei, int* __restrict__ cnt)
{
    int e = blockIdx.x * blockDim.x + threadIdx.x;
    if (e < EE) atomicAdd(cnt + __ldg(ei + 2 * e + 1), 1);
}
__global__ void csr_scan1(const int* __restrict__ cnt, int* __restrict__ bsum)
{
    __shared__ int s[256];
    int t = threadIdx.x, i = blockIdx.x * 256 + t;
    s[t] = (i < NN) ? cnt[i] : 0;
    __syncthreads();
    for (int o = 128; o > 0; o >>= 1) {
        if (t < o) s[t] += s[t + o];
        __syncthreads();
    }
    if (t == 0) bsum[blockIdx.x] = s[0];
}
__global__ void csr_scan2(int* __restrict__ bsum, int* __restrict__ rp)
{
    if (threadIdx.x == 0) {
        int run = 0;
        for (int b = 0; b < SCAN_B; b++) {
            int v = bsum[b];
            bsum[b] = run;
            run += v;
        }
        rp[NN] = run;
    }
}
__global__ void csr_scan3(const int* __restrict__ cnt, const int* __restrict__ bsum,
                          int* __restrict__ rp, int* __restrict__ cur)
{
    __shared__ int s[256];
    int t = threadIdx.x, i = blockIdx.x * 256 + t;
    int c = (i < NN) ? cnt[i] : 0;
    s[t] = c;
    __syncthreads();
    for (int o = 1; o < 256; o <<= 1) {
        int v = (t >= o) ? s[t - o] : 0;
        __syncthreads();
        s[t] += v;
        __syncthreads();
    }
    if (i < NN) {
        int excl = bsum[blockIdx.x] + s[t] - c;
        rp[i] = excl;
        cur[i] = excl;
    }
}
__global__ void csr_place(const int* __restrict__ ei, int* __restrict__ cur,
                          int* __restrict__ ssrc)
{
    int e = blockIdx.x * blockDim.x + threadIdx.x;
    if (e >= EE) return;
    int src = __ldg(ei + 2 * e);
    int dst = __ldg(ei + 2 * e + 1);
    int pos = atomicAdd(cur + dst, 1);
    ssrc[pos] = src;
}

// ---------------------------------------------------------------------------
// Atomic-free aggregate: out[d,:] = h[d,:] + sum_{e in row d} h[ssrc[e],:]
// ---------------------------------------------------------------------------
__global__ void __launch_bounds__(256) csr_agg(
    const float* __restrict__ h, const int* __restrict__ rp,
    const int* __restrict__ ssrc, float* __restrict__ out)
{
    int d = (blockIdx.x * blockDim.x + threadIdx.x) >> 5;
    if (d >= NN) return;
    int lane = threadIdx.x & 31;
    float4 acc = __ldg((const float4*)(h + (size_t)d * HD) + lane);
    int e = __ldg(rp + d), e1 = __ldg(rp + d + 1);
    for (; e + 4 <= e1; e += 4) {
        int s0 = __ldg(ssrc + e + 0);
        int s1 = __ldg(ssrc + e + 1);
        int s2 = __ldg(ssrc + e + 2);
        int s3 = __ldg(ssrc + e + 3);
        float4 v0 = __ldg((const float4*)(h + (size_t)s0 * HD) + lane);
        float4 v1 = __ldg((const float4*)(h + (size_t)s1 * HD) + lane);
        float4 v2 = __ldg((const float4*)(h + (size_t)s2 * HD) + lane);
        float4 v3 = __ldg((const float4*)(h + (size_t)s3 * HD) + lane);
        acc.x += (v0.x + v1.x) + (v2.x + v3.x);
        acc.y += (v0.y + v1.y) + (v2.y + v3.y);
        acc.z += (v0.z + v1.z) + (v2.z + v3.z);
        acc.w += (v0.w + v1.w) + (v2.w + v3.w);
    }
    for (; e < e1; ++e) {
        int s = __ldg(ssrc + e);
        float4 v = __ldg((const float4*)(h + (size_t)s * HD) + lane);
        acc.x += v.x; acc.y += v.y; acc.z += v.z; acc.w += v.w;
    }
    *((float4*)(out + (size_t)d * HD) + lane) = acc;
}

// ---------------------------------------------------------------------------
// Smem layouts (f16 single-pass: W 32KB, A 32KB)
// ---------------------------------------------------------------------------
#define SM_BB  0
#define SM_SC  512
#define SM_OF  1024
#define SM_W   1536
#define SM_A   (SM_W + 32768)            // 34304
#define RED_STRIDE 132
#define SM_BATCH (SM_W + 128 * RED_STRIDE * 4)   // 69120
#define SM_TOT (SM_BATCH + 512)          // 69632 (covers SEG red tile too)

#define F_BB1 0
#define F_SC  512
#define F_OF  1024
#define F_BB2 1536
#define F_W1  2048
#define F_W2  (F_W1 + 32768)
#define F_A   (F_W2 + 32768)
#define F_TOT (F_A + 32768)              // 100352

// Single-pass f16 mainloop: 8 k16-steps, A at abase0, W at wbase0.
#define MAINLOOP(d, abase0, wbase0)                                           \
    _Pragma("unroll")                                                         \
    for (int ch = 0; ch < 4; ++ch) {                                          \
        const u32 abase = (abase0) + ch * 8192;                               \
        const u32 wbase = (wbase0) + ch * 8192;                               \
        _Pragma("unroll")                                                     \
        for (int s = 0; s < 2; ++s) {                                         \
            u32 fa[2][4];                                                     \
            const int ar = wm * 32 + (lane & 7) + ((lane & 8) ? 8 : 0);       \
            const int aj = s * 2 + ((lane & 16) ? 1 : 0);                     \
            _Pragma("unroll")                                                 \
            for (int mt = 0; mt < 2; mt++) {                                  \
                int r = ar + mt * 16;                                         \
                u32 off = (u32)(r * 64 + ((aj ^ ((r >> 1) & 3)) << 4));       \
                ldsm4(fa[mt], abase + off);                                   \
            }                                                                 \
            u32 fb[4][2];                                                     \
            const int brb = wn * 32 + ((lane & 16) ? 8 : 0) + (lane & 7);     \
            const int bj = s * 2 + ((lane & 8) ? 1 : 0);                      \
            _Pragma("unroll")                                                 \
            for (int t = 0; t < 2; t++) {                                     \
                int r = brb + t * 16;                                         \
                u32 off = (u32)(r * 64 + ((bj ^ ((r >> 1) & 3)) << 4));       \
                u32 tmp[4];                                                   \
                ldsm4(tmp, wbase + off);                                      \
                fb[2 * t][0] = tmp[0]; fb[2 * t][1] = tmp[1];                 \
                fb[2 * t + 1][0] = tmp[2]; fb[2 * t + 1][1] = tmp[3];         \
            }                                                                 \
            _Pragma("unroll")                                                 \
            for (int mt = 0; mt < 2; mt++)                                    \
                _Pragma("unroll")                                             \
                for (int nt = 0; nt < 4; nt++)                                \
                    mma_f16(d[mt][nt], fa[mt], fb[nt]);                       \
        }                                                                     \
    }

// ---------------------------------------------------------------------------
// Fused layers 1+2: out = relu(bn1(relu(x@W1+b1))@W2+b2). f16 single-pass;
// phase-1 result restaged (f16, swizzled) into the A tile.
// ---------------------------------------------------------------------------
__global__ void __launch_bounds__(512, 1) gemm12(
    const float* __restrict__ A, const u16* __restrict__ w1sp,
    const u16* __restrict__ w2sp,
    const float* __restrict__ b1, const float* __restrict__ gam,
    const float* __restrict__ bet, const float* __restrict__ mmean,
    const float* __restrict__ mvar, const float* __restrict__ b2,
    float* __restrict__ out, int M)
{
    extern __shared__ char sm[];
    const u32 sb = smem_u32(sm);
    float* const bb1 = (float*)(sm + F_BB1);
    float* const scp = (float*)(sm + F_SC);
    float* const ofp = (float*)(sm + F_OF);
    float* const bb2 = (float*)(sm + F_BB2);

    const int tid = threadIdx.x, wid = tid >> 5, lane = tid & 31;
    const int g = lane >> 2, q = lane & 3;
    const int wm = wid & 3, wn = wid >> 2;
    const int row0 = blockIdx.x * 128;

    if (tid < 128) {
        bb1[tid] = b1[tid];
        float s = gam[tid] * rsqrtf(mvar[tid] + 1e-3f);
        scp[tid] = s;
        ofp[tid] = bet[tid] - mmean[tid] * s;
        bb2[tid] = b2[tid];
    }
    // W1 + W2 (64KB) via cp.async.
#pragma unroll
    for (int i = 0; i < 4; i++) {
        int idx = tid + i * 512;                 // 2048 x 16B each
        cp16(sb + F_W1 + idx * 16, (const char*)w1sp + idx * 16);
        cp16(sb + F_W2 + idx * 16, (const char*)w2sp + idx * 16);
    }
    // Stage x (f16).
    {
        const int j4 = lane * 4;
        const int ch = lane >> 3;
        const int kh = j4 & 31;
#pragma unroll
        for (int i = 0; i < 8; i++) {
            int r = wid * 8 + i;
            int grow = row0 + r;
            float4 v = make_float4(0.f, 0.f, 0.f, 0.f);
            if (grow < M)
                v = *(const float4*)(A + (size_t)grow * HD + j4);
            int hidx = swz_idx(r, kh);
            *(u32*)(sm + F_A + ch * 8192 + hidx * 2) = pack_h2(v.x, v.y);
            *(u32*)(sm + F_A + ch * 8192 + hidx * 2 + 4) = pack_h2(v.z, v.w);
        }
    }

    float d[2][4][4];
#pragma unroll
    for (int mt = 0; mt < 2; mt++)
#pragma unroll
        for (int nt = 0; nt < 4; nt++)
#pragma unroll
            for (int c = 0; c < 4; c++) d[mt][nt][c] = 0.f;

    asm volatile("cp.async.commit_group;" ::: "memory");
    asm volatile("cp.async.wait_group 0;" ::: "memory");
    __syncthreads();

    MAINLOOP(d, sb + F_A, sb + F_W1);

    // Mid-epilogue: bn1(relu(.+b1)) -> f16 restage into A tile.
    __syncthreads();
    const int q2 = q * 2;
#pragma unroll
    for (int mt = 0; mt < 2; mt++) {
        int lr = wm * 32 + mt * 16 + g;
#pragma unroll
        for (int nt = 0; nt < 4; nt++) {
            int col = wn * 32 + nt * 8 + q2;
            float s0 = scp[col], s1 = scp[col + 1];
            float o0 = ofp[col], o1 = ofp[col + 1];
            float B0 = bb1[col], B1 = bb1[col + 1];
            float v0 = fmaxf(d[mt][nt][0] + B0, 0.f) * s0 + o0;
            float v1 = fmaxf(d[mt][nt][1] + B1, 0.f) * s1 + o1;
            float v2 = fmaxf(d[mt][nt][2] + B0, 0.f) * s0 + o0;
            float v3 = fmaxf(d[mt][nt][3] + B1, 0.f) * s1 + o1;
            int ch = col >> 5, kh = col & 31;
            *(u32*)(sm + F_A + ch * 8192 + swz_idx(lr, kh) * 2) = pack_h2(v0, v1);
            *(u32*)(sm + F_A + ch * 8192 + swz_idx(lr + 8, kh) * 2) = pack_h2(v2, v3);
        }
    }
#pragma unroll
    for (int mt = 0; mt < 2; mt++)
#pragma unroll
        for (int nt = 0; nt < 4; nt++)
#pragma unroll
            for (int c = 0; c < 4; c++) d[mt][nt][c] = 0.f;
    __syncthreads();

    MAINLOOP(d, sb + F_A, sb + F_W2);

    // Final epilogue: relu(.+b2) -> out.
#pragma unroll
    for (int mt = 0; mt < 2; mt++) {
        int r0 = row0 + wm * 32 + mt * 16 + g;
#pragma unroll
        for (int nt = 0; nt < 4; nt++) {
            int col = wn * 32 + nt * 8 + q2;
            float B0 = bb2[col], B1 = bb2[col + 1];
            float v0 = fmaxf(d[mt][nt][0] + B0, 0.f);
            float v1 = fmaxf(d[mt][nt][1] + B1, 0.f);
            float v2 = fmaxf(d[mt][nt][2] + B0, 0.f);
            float v3 = fmaxf(d[mt][nt][3] + B1, 0.f);
            if (r0 < M)
                *(float2*)(out + (size_t)r0 * HD + col) = make_float2(v0, v1);
            if (r0 + 8 < M)
                *(float2*)(out + (size_t)(r0 + 8) * HD + col) = make_float2(v2, v3);
        }
    }
}

// ---------------------------------------------------------------------------
// Single f16 GEMM: out = epi(A@W + bias). SEG=true fuses the graph readout
// (sorted batch) into the epilogue via boundary-flush atomics.
// ---------------------------------------------------------------------------
template <bool DO_BN, bool SEG>
__global__ void __launch_bounds__(512, 1) gemm_f16(
    const float* __restrict__ A, const u16* __restrict__ wsp,
    const float* __restrict__ bias, const float* __restrict__ gam,
    const float* __restrict__ bet, const float* __restrict__ mmean,
    const float* __restrict__ mvar, float* __restrict__ out,
    const int* __restrict__ batch, float* __restrict__ gout, int M)
{
    extern __shared__ char sm[];
    const u32 sb = smem_u32(sm);
    float* const bbp = (float*)(sm + SM_BB);
    float* const scp = (float*)(sm + SM_SC);
    float* const ofp = (float*)(sm + SM_OF);

    const int tid = threadIdx.x, wid = tid >> 5, lane = tid & 31;
    const int g = lane >> 2, q = lane & 3;
    const int wm = wid & 3, wn = wid >> 2;
    const int row0 = blockIdx.x * 128;

    if (tid < 128) {
        bbp[tid] = bias[tid];
        float s = 1.f, o = 0.f;
        if (DO_BN) {
            s = gam[tid] * rsqrtf(mvar[tid] + 1e-3f);
            o = bet[tid] - mmean[tid] * s;
        }
        scp[tid] = s;
        ofp[tid] = o;
    }
#pragma unroll
    for (int i = 0; i < 4; i++) {
        int idx = tid + i * 512;
        cp16(sb + SM_W + idx * 16, (const char*)wsp + idx * 16);
    }
    {
        const int j4 = lane * 4;
        const int ch = lane >> 3;
        const int kh = j4 & 31;
#pragma unroll
        for (int i = 0; i < 8; i++) {
            int r = wid * 8 + i;
            int grow = row0 + r;
            float4 v = make_float4(0.f, 0.f, 0.f, 0.f);
            if (grow < M)
                v = *(const float4*)(A + (size_t)grow * HD + j4);
            int hidx = swz_idx(r, kh);
            *(u32*)(sm + SM_A + ch * 8192 + hidx * 2) = pack_h2(v.x, v.y);
            *(u32*)(sm + SM_A + ch * 8192 + hidx * 2 + 4) = pack_h2(v.z, v.w);
        }
    }

    float d[2][4][4];
#pragma unroll
    for (int mt = 0; mt < 2; mt++)
#pragma unroll
        for (int nt = 0; nt < 4; nt++)
#pragma unroll
            for (int c = 0; c < 4; c++) d[mt][nt][c] = 0.f;

    asm volatile("cp.async.commit_group;" ::: "memory");
    asm volatile("cp.async.wait_group 0;" ::: "memory");
    __syncthreads();

    MAINLOOP(d, sb + SM_A, sb + SM_W);

    const int q2 = q * 2;

    if (!SEG) {
#pragma unroll
        for (int mt = 0; mt < 2; mt++) {
            int r0 = row0 + wm * 32 + mt * 16 + g;
#pragma unroll
            for (int nt = 0; nt < 4; nt++) {
                int col = wn * 32 + nt * 8 + q2;
                float s0 = scp[col], s1 = scp[col + 1];
                float o0 = ofp[col], o1 = ofp[col + 1];
                float B0 = bbp[col], B1 = bbp[col + 1];
                float v0 = fmaxf(d[mt][nt][0] + B0, 0.f) * s0 + o0;
                float v1 = fmaxf(d[mt][nt][1] + B1, 0.f) * s1 + o1;
                float v2 = fmaxf(d[mt][nt][2] + B0, 0.f) * s0 + o0;
                float v3 = fmaxf(d[mt][nt][3] + B1, 0.f) * s1 + o1;
                if (r0 < M)
                    *(float2*)(out + (size_t)r0 * HD + col) = make_float2(v0, v1);
                if (r0 + 8 < M)
                    *(float2*)(out + (size_t)(r0 + 8) * HD + col) = make_float2(v2, v3);
            }
        }
    } else {
        // Fused segment-sum epilogue: stage tile into dead smem, reduce by
        // sorted batch id, boundary-flush atomics into gout.
        float* red = (float*)(sm + SM_W);
        int* bsm = (int*)(sm + SM_BATCH);
        __syncthreads();
#pragma unroll
        for (int mt = 0; mt < 2; mt++) {
            int lr = wm * 32 + mt * 16 + g;
            bool ok0 = (row0 + lr < M), ok1 = (row0 + lr + 8 < M);
#pragma unroll
            for (int nt = 0; nt < 4; nt++) {
                int col = wn * 32 + nt * 8 + q2;
                float B0 = bbp[col], B1 = bbp[col + 1];
                float v0 = ok0 ? fmaxf(d[mt][nt][0] + B0, 0.f) : 0.f;
                float v1 = ok0 ? fmaxf(d[mt][nt][1] + B1, 0.f) : 0.f;
                float v2 = ok1 ? fmaxf(d[mt][nt][2] + B0, 0.f) : 0.f;
                float v3 = ok1 ? fmaxf(d[mt][nt][3] + B1, 0.f) : 0.f;
                *(float2*)&red[lr * RED_STRIDE + col] = make_float2(v0, v1);
                *(float2*)&red[(lr + 8) * RED_STRIDE + col] = make_float2(v2, v3);
            }
        }
        if (tid < 128)
            bsm[tid] = (row0 + tid < M) ? __ldg(batch + row0 + tid) : -1;
        __syncthreads();
        const int c = tid & 127, part = tid >> 7;
        const int rb = part * 32;
        float acc = 0.f;
        int curb = bsm[rb];
#pragma unroll
        for (int r = 0; r < 32; ++r) {
            int b = bsm[rb + r];
            if (b != curb) {
                if (curb >= 0) atomicAdd(gout + (size_t)curb * HD + c, acc);
                acc = 0.f;
                curb = b;
            }
            acc += red[(rb + r) * RED_STRIDE + c];
        }
        if (curb >= 0) atomicAdd(gout + (size_t)curb * HD + c, acc);
    }
}

__global__ void zero_out(float* __restrict__ out, int n)
{
    int t = blockIdx.x * blockDim.x + threadIdx.x;
    if (t < n) out[t] = 0.f;
}

extern "C" void kernel_launch(void* const* d_in, const int* in_sizes, int n_in,
                              void* d_out, int out_size)
{
    const float* x   = (const float*)d_in[0];
    const int*   ei  = (const int*)d_in[1];
    const int*   bat = (const int*)d_in[2];
    const float* W1  = (const float*)d_in[3];
    const float* b1  = (const float*)d_in[4];
    const float* g1  = (const float*)d_in[5];
    const float* be1 = (const float*)d_in[6];
    const float* mm1 = (const float*)d_in[7];
    const float* mv1 = (const float*)d_in[8];
    const float* W2  = (const float*)d_in[9];
    const float* b2  = (const float*)d_in[10];
    const float* W3  = (const float*)d_in[11];
    const float* b3  = (const float*)d_in[12];
    const float* g2  = (const float*)d_in[13];
    const float* be2 = (const float*)d_in[14];
    const float* mm2 = (const float*)d_in[15];
    const float* mv2 = (const float*)d_in[16];
    const float* W4  = (const float*)d_in[17];
    const float* b4  = (const float*)d_in[18];
    float* out = (float*)d_out;

    float *bufA, *bufB, *bufC;
    u16* wsp;
    int *rp, *cur, *ssrc, *bsum;
    cudaGetSymbolAddress((void**)&bufA, g_bufA);
    cudaGetSymbolAddress((void**)&bufB, g_bufB);
    cudaGetSymbolAddress((void**)&bufC, g_bufC);
    cudaGetSymbolAddress((void**)&wsp, g_wsp);
    cudaGetSymbolAddress((void**)&rp, g_rp);
    cudaGetSymbolAddress((void**)&cur, g_cur);
    cudaGetSymbolAddress((void**)&ssrc, g_ssrc);
    cudaGetSymbolAddress((void**)&bsum, g_bsum);

    cudaFuncSetAttribute(gemm12,
                         cudaFuncAttributeMaxDynamicSharedMemorySize, F_TOT);
    cudaFuncSetAttribute(gemm_f16<true, false>,
                         cudaFuncAttributeMaxDynamicSharedMemorySize, SM_TOT);
    cudaFuncSetAttribute(gemm_f16<false, true>,
                         cudaFuncAttributeMaxDynamicSharedMemorySize, SM_TOT);

    static cudaStream_t s2 = nullptr;
    static cudaEvent_t evFork = nullptr, evJoin = nullptr;
    if (s2 == nullptr) {
        cudaStreamCreateWithFlags(&s2, cudaStreamNonBlocking);
        cudaEventCreateWithFlags(&evFork, cudaEventDisableTiming);
        cudaEventCreateWithFlags(&evJoin, cudaEventDisableTiming);
    }

    const int gemm_blocks = (NN + 127) / 128;          // 391
    const int edge_blocks = (EE + 255) / 256;
    const int agg_blocks  = (NN * 32 + 255) / 256;

    // Main: W prep; fork CSR build + output zeroing to s2 (evJoin AFTER
    // zero_out so the fused seg atomics are ordered after the zeroing).
    prep_w<<<256, 256>>>(W1, W2, W3, W4, wsp);
    cudaEventRecord(evFork, 0);
    cudaStreamWaitEvent(s2, evFork, 0);
    csr_zero<<<(NN + 255) / 256, 256, 0, s2>>>(cur);
    csr_hist<<<edge_blocks, 256, 0, s2>>>(ei, cur);
    csr_scan1<<<SCAN_B, 256, 0, s2>>>(cur, bsum);
    csr_scan2<<<1, 32, 0, s2>>>(bsum, rp);
    csr_scan3<<<SCAN_B, 256, 0, s2>>>(cur, bsum, rp, cur);
    csr_place<<<edge_blocks, 256, 0, s2>>>(ei, cur, ssrc);
    zero_out<<<(GG * HD + 255) / 256, 256, 0, s2>>>(out, GG * HD);
    cudaEventRecord(evJoin, s2);

    // Fused layers 1+2: x -> bufB (overlaps CSR build).
    gemm12<<<gemm_blocks, 512, F_TOT>>>(
        x, wsp + 0 * 16384, wsp + 1 * 16384,
        b1, g1, be1, mm1, mv1, b2, bufB, NN);

    // Join: csr_agg needs the CSR arrays (and transitively zero_out done).
    cudaStreamWaitEvent(0, evJoin, 0);

    // bufC = bufB + aggregate(bufB)
    csr_agg<<<agg_blocks, 256>>>(bufB, rp, ssrc, bufC);
    // h = bn2(relu(bufC@W3+b3))  bufC -> bufA
    gemm_f16<true, false><<<gemm_blocks, 512, SM_TOT>>>(
        bufC, wsp + 2 * 16384, b3, g2, be2, mm2, mv2, bufA, nullptr, nullptr, NN);
    // bufB = bufA + aggregate(bufA)
    csr_agg<<<agg_blocks, 256>>>(bufA, rp, ssrc, bufB);
    // out += segsum(relu(bufB@W4+b4))  fused epilogue
    gemm_f16<false, true><<<gemm_blocks, 512, SM_TOT>>>(
        bufB, wsp + 3 * 16384, b4, nullptr, nullptr, nullptr, nullptr,
        nullptr, bat, out, NN);
}

// round 16
// speedup vs baseline: 1.5763x; 1.1186x over previous
#include <cuda_runtime.h>
#include <cuda_fp16.h>

#define NN 50000
#define HD 128
#define EE 640000
#define GG 128

typedef unsigned int u32;
typedef unsigned short u16;
typedef unsigned long long u64;

// Inter-layer buffers now f16 (12.8 MB each).
__device__ __align__(16) u16 g_bufA[NN * HD];
__device__ __align__(16) u16 g_bufB[NN * HD];
__device__ __align__(16) u16 g_bufC[NN * HD];
// Pre-converted W: [layer][16384 halves] (f16, transposed, swizzled image).
__device__ __align__(16) u16 g_wsp[4 * 16384];
// CSR-by-dst scratch
__device__ int g_rp[NN + 1];
__device__ int g_cur[NN];
__device__ int g_ssrc[EE];
__device__ int g_bsum[256];

#define SCAN_B 196

__device__ __forceinline__ u32 smem_u32(const void* p) {
    u32 a;
    asm("{ .reg .u64 t; cvta.to.shared.u64 t, %1; cvt.u32.u64 %0, t; }"
        : "=r"(a) : "l"(p));
    return a;
}
__device__ __forceinline__ void mma_f16(float* d, const u32* a, const u32* b) {
    asm("mma.sync.aligned.m16n8k16.row.col.f32.f16.f16.f32 "
        "{%0,%1,%2,%3}, {%4,%5,%6,%7}, {%8,%9}, {%0,%1,%2,%3};"
        : "+f"(d[0]), "+f"(d[1]), "+f"(d[2]), "+f"(d[3])
        : "r"(a[0]), "r"(a[1]), "r"(a[2]), "r"(a[3]), "r"(b[0]), "r"(b[1]));
}
__device__ __forceinline__ void ldsm4(u32* r, u32 addr) {
    asm volatile("ldmatrix.sync.aligned.m8n8.x4.shared.b16 {%0,%1,%2,%3}, [%4];"
                 : "=r"(r[0]), "=r"(r[1]), "=r"(r[2]), "=r"(r[3]) : "r"(addr));
}
__device__ __forceinline__ void cp16(u32 smem, const void* g) {
    asm volatile("cp.async.cg.shared.global [%0], [%1], 16;"
                 :: "r"(smem), "l"(g) : "memory");
}
__device__ __forceinline__ int swz_idx(int r, int kh) {
    return r * 32 + ((((kh >> 3) ^ ((r >> 1) & 3)) << 3) | (kh & 7));
}
__device__ __forceinline__ u32 pack_h2(float v0, float v1) {
    __half h0 = __float2half_rn(v0), h1 = __float2half_rn(v1);
    return (u32)__half_as_ushort(h0) | ((u32)__half_as_ushort(h1) << 16);
}
__device__ __forceinline__ float4 h4_to_f4(u64 v) {
    u32 lo = (u32)v, hi = (u32)(v >> 32);
    float2 f0 = __half22float2(*(__half2*)&lo);
    float2 f1 = __half22float2(*(__half2*)&hi);
    return make_float4(f0.x, f0.y, f1.x, f1.y);
}
__device__ __forceinline__ u64 f4_to_h4(float4 v) {
    return (u64)pack_h2(v.x, v.y) | ((u64)pack_h2(v.z, v.w) << 32);
}

// ---------------------------------------------------------------------------
// W prep: f16 convert, transposed [n][k], k-chunked (4x32), swizzled.
// ---------------------------------------------------------------------------
__global__ void prep_w(const float* __restrict__ W1, const float* __restrict__ W2,
                       const float* __restrict__ W3, const float* __restrict__ W4,
                       u16* __restrict__ out)
{
    int t = blockIdx.x * 256 + threadIdx.x;
    int layer = t >> 14, e = t & 16383;
    int k = e >> 7, n = e & 127;
    const float* W = layer == 0 ? W1 : layer == 1 ? W2 : layer == 2 ? W3 : W4;
    float v = W[k * HD + n];
    int ch = k >> 5, kh = k & 31;
    out[layer * 16384 + ch * 4096 + swz_idx(n, kh)] =
        __half_as_ushort(__float2half_rn(v));
}

// ---------------------------------------------------------------------------
// CSR build
// ---------------------------------------------------------------------------
__global__ void csr_zero(int* __restrict__ cnt)
{
    int t = blockIdx.x * blockDim.x + threadIdx.x;
    if (t < NN) cnt[t] = 0;
}
__global__ void csr_hist(const int* __restrict__ ei, int* __restrict__ cnt)
{
    int e = blockIdx.x * blockDim.x + threadIdx.x;
    if (e < EE) atomicAdd(cnt + __ldg(ei + 2 * e + 1), 1);
}
__global__ void csr_scan1(const int* __restrict__ cnt, int* __restrict__ bsum)
{
    __shared__ int s[256];
    int t = threadIdx.x, i = blockIdx.x * 256 + t;
    s[t] = (i < NN) ? cnt[i] : 0;
    __syncthreads();
    for (int o = 128; o > 0; o >>= 1) {
        if (t < o) s[t] += s[t + o];
        __syncthreads();
    }
    if (t == 0) bsum[blockIdx.x] = s[0];
}
__global__ void csr_scan2(int* __restrict__ bsum, int* __restrict__ rp)
{
    if (threadIdx.x == 0) {
        int run = 0;
        for (int b = 0; b < SCAN_B; b++) {
            int v = bsum[b];
            bsum[b] = run;
            run += v;
        }
        rp[NN] = run;
    }
}
__global__ void csr_scan3(const int* __restrict__ cnt, const int* __restrict__ bsum,
                          int* __restrict__ rp, int* __restrict__ cur)
{
    __shared__ int s[256];
    int t = threadIdx.x, i = blockIdx.x * 256 + t;
    int c = (i < NN) ? cnt[i] : 0;
    s[t] = c;
    __syncthreads();
    for (int o = 1; o < 256; o <<= 1) {
        int v = (t >= o) ? s[t - o] : 0;
        __syncthreads();
        s[t] += v;
        __syncthreads();
    }
    if (i < NN) {
        int excl = bsum[blockIdx.x] + s[t] - c;
        rp[i] = excl;
        cur[i] = excl;
    }
}
__global__ void csr_place(const int* __restrict__ ei, int* __restrict__ cur,
                          int* __restrict__ ssrc)
{
    int e = blockIdx.x * blockDim.x + threadIdx.x;
    if (e >= EE) return;
    int src = __ldg(ei + 2 * e);
    int dst = __ldg(ei + 2 * e + 1);
    int pos = atomicAdd(cur + dst, 1);
    ssrc[pos] = src;
}

// ---------------------------------------------------------------------------
// Atomic-free aggregate (f16 in/out, fp32 accumulate):
// out[d,:] = h[d,:] + sum_{e in row d} h[ssrc[e],:]
// One warp per dst; lane handles 4 halves (one u64) per row.
// ---------------------------------------------------------------------------
__global__ void __launch_bounds__(256) csr_agg(
    const u16* __restrict__ h, const int* __restrict__ rp,
    const int* __restrict__ ssrc, u16* __restrict__ out)
{
    int d = (blockIdx.x * blockDim.x + threadIdx.x) >> 5;
    if (d >= NN) return;
    int lane = threadIdx.x & 31;
    float4 acc = h4_to_f4(__ldg((const u64*)(h + (size_t)d * HD) + lane));
    int e = __ldg(rp + d), e1 = __ldg(rp + d + 1);
    for (; e + 4 <= e1; e += 4) {
        int s0 = __ldg(ssrc + e + 0);
        int s1 = __ldg(ssrc + e + 1);
        int s2 = __ldg(ssrc + e + 2);
        int s3 = __ldg(ssrc + e + 3);
        float4 v0 = h4_to_f4(__ldg((const u64*)(h + (size_t)s0 * HD) + lane));
        float4 v1 = h4_to_f4(__ldg((const u64*)(h + (size_t)s1 * HD) + lane));
        float4 v2 = h4_to_f4(__ldg((const u64*)(h + (size_t)s2 * HD) + lane));
        float4 v3 = h4_to_f4(__ldg((const u64*)(h + (size_t)s3 * HD) + lane));
        acc.x += (v0.x + v1.x) + (v2.x + v3.x);
        acc.y += (v0.y + v1.y) + (v2.y + v3.y);
        acc.z += (v0.z + v1.z) + (v2.z + v3.z);
        acc.w += (v0.w + v1.w) + (v2.w + v3.w);
    }
    for (; e < e1; ++e) {
        int s = __ldg(ssrc + e);
        float4 v = h4_to_f4(__ldg((const u64*)(h + (size_t)s * HD) + lane));
        acc.x += v.x; acc.y += v.y; acc.z += v.z; acc.w += v.w;
    }
    ((u64*)(out + (size_t)d * HD))[lane] = f4_to_h4(acc);
}

// ---------------------------------------------------------------------------
// Smem layouts (f16 single-pass: W 32KB, A 32KB)
// ---------------------------------------------------------------------------
#define SM_BB  0
#define SM_SC  512
#define SM_OF  1024
#define SM_W   1536
#define SM_A   (SM_W + 32768)            // 34304
#define RED_STRIDE 132
#define SM_BATCH (SM_W + 128 * RED_STRIDE * 4)   // 69120
#define SM_TOT (SM_BATCH + 512)          // 69632

#define F_BB1 0
#define F_SC  512
#define F_OF  1024
#define F_BB2 1536
#define F_W1  2048
#define F_W2  (F_W1 + 32768)
#define F_A   (F_W2 + 32768)
#define F_TOT (F_A + 32768)              // 100352

// Single-pass f16 mainloop: 8 k16-steps, A at abase0, W at wbase0.
#define MAINLOOP(d, abase0, wbase0)                                           \
    _Pragma("unroll")                                                         \
    for (int ch = 0; ch < 4; ++ch) {                                          \
        const u32 abase = (abase0) + ch * 8192;                               \
        const u32 wbase = (wbase0) + ch * 8192;                               \
        _Pragma("unroll")                                                     \
        for (int s = 0; s < 2; ++s) {                                         \
            u32 fa[2][4];                                                     \
            const int ar = wm * 32 + (lane & 7) + ((lane & 8) ? 8 : 0);       \
            const int aj = s * 2 + ((lane & 16) ? 1 : 0);                     \
            _Pragma("unroll")                                                 \
            for (int mt = 0; mt < 2; mt++) {                                  \
                int r = ar + mt * 16;                                         \
                u32 off = (u32)(r * 64 + ((aj ^ ((r >> 1) & 3)) << 4));       \
                ldsm4(fa[mt], abase + off);                                   \
            }                                                                 \
            u32 fb[4][2];                                                     \
            const int brb = wn * 32 + ((lane & 16) ? 8 : 0) + (lane & 7);     \
            const int bj = s * 2 + ((lane & 8) ? 1 : 0);                      \
            _Pragma("unroll")                                                 \
            for (int t = 0; t < 2; t++) {                                     \
                int r = brb + t * 16;                                         \
                u32 off = (u32)(r * 64 + ((bj ^ ((r >> 1) & 3)) << 4));       \
                u32 tmp[4];                                                   \
                ldsm4(tmp, wbase + off);                                      \
                fb[2 * t][0] = tmp[0]; fb[2 * t][1] = tmp[1];                 \
                fb[2 * t + 1][0] = tmp[2]; fb[2 * t + 1][1] = tmp[3];         \
            }                                                                 \
            _Pragma("unroll")                                                 \
            for (int mt = 0; mt < 2; mt++)                                    \
                _Pragma("unroll")                                             \
                for (int nt = 0; nt < 4; nt++)                                \
                    mma_f16(d[mt][nt], fa[mt], fb[nt]);                       \
        }                                                                     \
    }

// ---------------------------------------------------------------------------
// Fused layers 1+2: bufB(f16) = relu(bn1(relu(x@W1+b1))@W2+b2). x is fp32.
// ---------------------------------------------------------------------------
__global__ void __launch_bounds__(512, 1) gemm12(
    const float* __restrict__ A, const u16* __restrict__ w1sp,
    const u16* __restrict__ w2sp,
    const float* __restrict__ b1, const float* __restrict__ gam,
    const float* __restrict__ bet, const float* __restrict__ mmean,
    const float* __restrict__ mvar, const float* __restrict__ b2,
    u16* __restrict__ out, int M)
{
    extern __shared__ char sm[];
    const u32 sb = smem_u32(sm);
    float* const bb1 = (float*)(sm + F_BB1);
    float* const scp = (float*)(sm + F_SC);
    float* const ofp = (float*)(sm + F_OF);
    float* const bb2 = (float*)(sm + F_BB2);

    const int tid = threadIdx.x, wid = tid >> 5, lane = tid & 31;
    const int g = lane >> 2, q = lane & 3;
    const int wm = wid & 3, wn = wid >> 2;
    const int row0 = blockIdx.x * 128;

    if (tid < 128) {
        bb1[tid] = b1[tid];
        float s = gam[tid] * rsqrtf(mvar[tid] + 1e-3f);
        scp[tid] = s;
        ofp[tid] = bet[tid] - mmean[tid] * s;
        bb2[tid] = b2[tid];
    }
#pragma unroll
    for (int i = 0; i < 4; i++) {
        int idx = tid + i * 512;
        cp16(sb + F_W1 + idx * 16, (const char*)w1sp + idx * 16);
        cp16(sb + F_W2 + idx * 16, (const char*)w2sp + idx * 16);
    }
    // Stage x (fp32 -> f16).
    {
        const int j4 = lane * 4;
        const int ch = lane >> 3;
        const int kh = j4 & 31;
#pragma unroll
        for (int i = 0; i < 8; i++) {
            int r = wid * 8 + i;
            int grow = row0 + r;
            float4 v = make_float4(0.f, 0.f, 0.f, 0.f);
            if (grow < M)
                v = *(const float4*)(A + (size_t)grow * HD + j4);
            int hidx = swz_idx(r, kh);
            *(u32*)(sm + F_A + ch * 8192 + hidx * 2) = pack_h2(v.x, v.y);
            *(u32*)(sm + F_A + ch * 8192 + hidx * 2 + 4) = pack_h2(v.z, v.w);
        }
    }

    float d[2][4][4];
#pragma unroll
    for (int mt = 0; mt < 2; mt++)
#pragma unroll
        for (int nt = 0; nt < 4; nt++)
#pragma unroll
            for (int c = 0; c < 4; c++) d[mt][nt][c] = 0.f;

    asm volatile("cp.async.commit_group;" ::: "memory");
    asm volatile("cp.async.wait_group 0;" ::: "memory");
    __syncthreads();

    MAINLOOP(d, sb + F_A, sb + F_W1);

    // Mid-epilogue: bn1(relu(.+b1)) -> f16 restage into A tile.
    __syncthreads();
    const int q2 = q * 2;
#pragma unroll
    for (int mt = 0; mt < 2; mt++) {
        int lr = wm * 32 + mt * 16 + g;
#pragma unroll
        for (int nt = 0; nt < 4; nt++) {
            int col = wn * 32 + nt * 8 + q2;
            float s0 = scp[col], s1 = scp[col + 1];
            float o0 = ofp[col], o1 = ofp[col + 1];
            float B0 = bb1[col], B1 = bb1[col + 1];
            float v0 = fmaxf(d[mt][nt][0] + B0, 0.f) * s0 + o0;
            float v1 = fmaxf(d[mt][nt][1] + B1, 0.f) * s1 + o1;
            float v2 = fmaxf(d[mt][nt][2] + B0, 0.f) * s0 + o0;
            float v3 = fmaxf(d[mt][nt][3] + B1, 0.f) * s1 + o1;
            int ch = col >> 5, kh = col & 31;
            *(u32*)(sm + F_A + ch * 8192 + swz_idx(lr, kh) * 2) = pack_h2(v0, v1);
            *(u32*)(sm + F_A + ch * 8192 + swz_idx(lr + 8, kh) * 2) = pack_h2(v2, v3);
        }
    }
#pragma unroll
    for (int mt = 0; mt < 2; mt++)
#pragma unroll
        for (int nt = 0; nt < 4; nt++)
#pragma unroll
            for (int c = 0; c < 4; c++) d[mt][nt][c] = 0.f;
    __syncthreads();

    MAINLOOP(d, sb + F_A, sb + F_W2);

    // Final epilogue: relu(.+b2) -> f16 out.
#pragma unroll
    for (int mt = 0; mt < 2; mt++) {
        int r0 = row0 + wm * 32 + mt * 16 + g;
#pragma unroll
        for (int nt = 0; nt < 4; nt++) {
            int col = wn * 32 + nt * 8 + q2;
            float B0 = bb2[col], B1 = bb2[col + 1];
            float v0 = fmaxf(d[mt][nt][0] + B0, 0.f);
            float v1 = fmaxf(d[mt][nt][1] + B1, 0.f);
            float v2 = fmaxf(d[mt][nt][2] + B0, 0.f);
            float v3 = fmaxf(d[mt][nt][3] + B1, 0.f);
            if (r0 < M)
                *(u32*)(out + (size_t)r0 * HD + col) = pack_h2(v0, v1);
            if (r0 + 8 < M)
                *(u32*)(out + (size_t)(r0 + 8) * HD + col) = pack_h2(v2, v3);
        }
    }
}

// ---------------------------------------------------------------------------
// Single f16 GEMM, f16 input: out = epi(A@W + bias). SEG=true fuses the
// graph readout (sorted batch) via boundary-flush atomics into gout (fp32).
// A staging is a pure cp.async 16B copy (input already f16).
// ---------------------------------------------------------------------------
template <bool DO_BN, bool SEG>
__global__ void __launch_bounds__(512, 1) gemm_f16(
    const u16* __restrict__ A, const u16* __restrict__ wsp,
    const float* __restrict__ bias, const float* __restrict__ gam,
    const float* __restrict__ bet, const float* __restrict__ mmean,
    const float* __restrict__ mvar, u16* __restrict__ out,
    const int* __restrict__ batch, float* __restrict__ gout, int M)
{
    extern __shared__ char sm[];
    const u32 sb = smem_u32(sm);
    float* const bbp = (float*)(sm + SM_BB);
    float* const scp = (float*)(sm + SM_SC);
    float* const ofp = (float*)(sm + SM_OF);

    const int tid = threadIdx.x, wid = tid >> 5, lane = tid & 31;
    const int g = lane >> 2, q = lane & 3;
    const int wm = wid & 3, wn = wid >> 2;
    const int row0 = blockIdx.x * 128;

    if (tid < 128) {
        bbp[tid] = bias[tid];
        float s = 1.f, o = 0.f;
        if (DO_BN) {
            s = gam[tid] * rsqrtf(mvar[tid] + 1e-3f);
            o = bet[tid] - mmean[tid] * s;
        }
        scp[tid] = s;
        ofp[tid] = o;
    }
#pragma unroll
    for (int i = 0; i < 4; i++) {
        int idx = tid + i * 512;
        cp16(sb + SM_W + idx * 16, (const char*)wsp + idx * 16);
    }
    // A staging: 128 rows x 16 groups of 8 halves = 2048 x 16B cp.async.
#pragma unroll
    for (int i = 0; i < 4; i++) {
        int idx = tid + i * 512;             // 0..2047
        int r = idx >> 4;                    // 0..127
        int kh8 = (idx & 15) * 8;            // 0..120
        int ch = kh8 >> 5;
        int khin = kh8 & 31;
        u32 off = SM_A + ch * 8192 + (u32)swz_idx(r, khin) * 2;
        int grow = row0 + r;
        if (grow < M)
            cp16(sb + off, A + (size_t)grow * HD + kh8);
        else
            *(float4*)(sm + off) = make_float4(0.f, 0.f, 0.f, 0.f);
    }

    float d[2][4][4];
#pragma unroll
    for (int mt = 0; mt < 2; mt++)
#pragma unroll
        for (int nt = 0; nt < 4; nt++)
#pragma unroll
            for (int c = 0; c < 4; c++) d[mt][nt][c] = 0.f;

    asm volatile("cp.async.commit_group;" ::: "memory");
    asm volatile("cp.async.wait_group 0;" ::: "memory");
    __syncthreads();

    MAINLOOP(d, sb + SM_A, sb + SM_W);

    const int q2 = q * 2;

    if (!SEG) {
#pragma unroll
        for (int mt = 0; mt < 2; mt++) {
            int r0 = row0 + wm * 32 + mt * 16 + g;
#pragma unroll
            for (int nt = 0; nt < 4; nt++) {
                int col = wn * 32 + nt * 8 + q2;
                float s0 = scp[col], s1 = scp[col + 1];
                float o0 = ofp[col], o1 = ofp[col + 1];
                float B0 = bbp[col], B1 = bbp[col + 1];
                float v0 = fmaxf(d[mt][nt][0] + B0, 0.f) * s0 + o0;
                float v1 = fmaxf(d[mt][nt][1] + B1, 0.f) * s1 + o1;
                float v2 = fmaxf(d[mt][nt][2] + B0, 0.f) * s0 + o0;
                float v3 = fmaxf(d[mt][nt][3] + B1, 0.f) * s1 + o1;
                if (r0 < M)
                    *(u32*)(out + (size_t)r0 * HD + col) = pack_h2(v0, v1);
                if (r0 + 8 < M)
                    *(u32*)(out + (size_t)(r0 + 8) * HD + col) = pack_h2(v2, v3);
            }
        }
    } else {
        // Fused segment-sum epilogue (fp32 smem staging + atomics).
        float* red = (float*)(sm + SM_W);
        int* bsm = (int*)(sm + SM_BATCH);
        __syncthreads();
#pragma unroll
        for (int mt = 0; mt < 2; mt++) {
            int lr = wm * 32 + mt * 16 + g;
            bool ok0 = (row0 + lr < M), ok1 = (row0 + lr + 8 < M);
#pragma unroll
            for (int nt = 0; nt < 4; nt++) {
                int col = wn * 32 + nt * 8 + q2;
                float B0 = bbp[col], B1 = bbp[col + 1];
                float v0 = ok0 ? fmaxf(d[mt][nt][0] + B0, 0.f) : 0.f;
                float v1 = ok0 ? fmaxf(d[mt][nt][1] + B1, 0.f) : 0.f;
                float v2 = ok1 ? fmaxf(d[mt][nt][2] + B0, 0.f) : 0.f;
                float v3 = ok1 ? fmaxf(d[mt][nt][3] + B1, 0.f) : 0.f;
                *(float2*)&red[lr * RED_STRIDE + col] = make_float2(v0, v1);
                *(float2*)&red[(lr + 8) * RED_STRIDE + col] = make_float2(v2, v3);
            }
        }
        if (tid < 128)
            bsm[tid] = (row0 + tid < M) ? __ldg(batch + row0 + tid) : -1;
        __syncthreads();
        const int c = tid & 127, part = tid >> 7;
        const int rb = part * 32;
        float acc = 0.f;
        int curb = bsm[rb];
#pragma unroll
        for (int r = 0; r < 32; ++r) {
            int b = bsm[rb + r];
            if (b != curb) {
                if (curb >= 0) atomicAdd(gout + (size_t)curb * HD + c, acc);
                acc = 0.f;
                curb = b;
            }
            acc += red[(rb + r) * RED_STRIDE + c];
        }
        if (curb >= 0) atomicAdd(gout + (size_t)curb * HD + c, acc);
    }
}

__global__ void zero_out(float* __restrict__ out, int n)
{
    int t = blockIdx.x * blockDim.x + threadIdx.x;
    if (t < n) out[t] = 0.f;
}

extern "C" void kernel_launch(void* const* d_in, const int* in_sizes, int n_in,
                              void* d_out, int out_size)
{
    const float* x   = (const float*)d_in[0];
    const int*   ei  = (const int*)d_in[1];
    const int*   bat = (const int*)d_in[2];
    const float* W1  = (const float*)d_in[3];
    const float* b1  = (const float*)d_in[4];
    const float* g1  = (const float*)d_in[5];
    const float* be1 = (const float*)d_in[6];
    const float* mm1 = (const float*)d_in[7];
    const float* mv1 = (const float*)d_in[8];
    const float* W2  = (const float*)d_in[9];
    const float* b2  = (const float*)d_in[10];
    const float* W3  = (const float*)d_in[11];
    const float* b3  = (const float*)d_in[12];
    const float* g2  = (const float*)d_in[13];
    const float* be2 = (const float*)d_in[14];
    const float* mm2 = (const float*)d_in[15];
    const float* mv2 = (const float*)d_in[16];
    const float* W4  = (const float*)d_in[17];
    const float* b4  = (const float*)d_in[18];
    float* out = (float*)d_out;

    u16 *bufA, *bufB, *bufC, *wsp;
    int *rp, *cur, *ssrc, *bsum;
    cudaGetSymbolAddress((void**)&bufA, g_bufA);
    cudaGetSymbolAddress((void**)&bufB, g_bufB);
    cudaGetSymbolAddress((void**)&bufC, g_bufC);
    cudaGetSymbolAddress((void**)&wsp, g_wsp);
    cudaGetSymbolAddress((void**)&rp, g_rp);
    cudaGetSymbolAddress((void**)&cur, g_cur);
    cudaGetSymbolAddress((void**)&ssrc, g_ssrc);
    cudaGetSymbolAddress((void**)&bsum, g_bsum);

    cudaFuncSetAttribute(gemm12,
                         cudaFuncAttributeMaxDynamicSharedMemorySize, F_TOT);
    cudaFuncSetAttribute(gemm_f16<true, false>,
                         cudaFuncAttributeMaxDynamicSharedMemorySize, SM_TOT);
    cudaFuncSetAttribute(gemm_f16<false, true>,
                         cudaFuncAttributeMaxDynamicSharedMemorySize, SM_TOT);

    static cudaStream_t s2 = nullptr;
    static cudaEvent_t evFork = nullptr, evJoin = nullptr;
    if (s2 == nullptr) {
        cudaStreamCreateWithFlags(&s2, cudaStreamNonBlocking);
        cudaEventCreateWithFlags(&evFork, cudaEventDisableTiming);
        cudaEventCreateWithFlags(&evJoin, cudaEventDisableTiming);
    }

    const int gemm_blocks = (NN + 127) / 128;          // 391
    const int edge_blocks = (EE + 255) / 256;
    const int agg_blocks  = (NN * 32 + 255) / 256;

    // Main: W prep; fork CSR build + output zeroing to s2 (evJoin AFTER
    // zero_out so the fused seg atomics are ordered after the zeroing).
    prep_w<<<256, 256>>>(W1, W2, W3, W4, wsp);
    cudaEventRecord(evFork, 0);
    cudaStreamWaitEvent(s2, evFork, 0);
    csr_zero<<<(NN + 255) / 256, 256, 0, s2>>>(cur);
    csr_hist<<<edge_blocks, 256, 0, s2>>>(ei, cur);
    csr_scan1<<<SCAN_B, 256, 0, s2>>>(cur, bsum);
    csr_scan2<<<1, 32, 0, s2>>>(bsum, rp);
    csr_scan3<<<SCAN_B, 256, 0, s2>>>(cur, bsum, rp, cur);
    csr_place<<<edge_blocks, 256, 0, s2>>>(ei, cur, ssrc);
    zero_out<<<(GG * HD + 255) / 256, 256, 0, s2>>>(out, GG * HD);
    cudaEventRecord(evJoin, s2);

    // Fused layers 1+2: x -> bufB(f16) (overlaps CSR build).
    gemm12<<<gemm_blocks, 512, F_TOT>>>(
        x, wsp + 0 * 16384, wsp + 1 * 16384,
        b1, g1, be1, mm1, mv1, b2, bufB, NN);

    // Join: csr_agg needs the CSR arrays (and transitively zero_out done).
    cudaStreamWaitEvent(0, evJoin, 0);

    // bufC = bufB + aggregate(bufB)   (f16)
    csr_agg<<<agg_blocks, 256>>>(bufB, rp, ssrc, bufC);
    // bufA = bn2(relu(bufC@W3+b3))    (f16)
    gemm_f16<true, false><<<gemm_blocks, 512, SM_TOT>>>(
        bufC, wsp + 2 * 16384, b3, g2, be2, mm2, mv2, bufA, nullptr, nullptr, NN);
    // bufB = bufA + aggregate(bufA)   (f16)
    csr_agg<<<agg_blocks, 256>>>(bufA, rp, ssrc, bufB);
    // out += segsum(relu(bufB@W4+b4)) fused epilogue
    gemm_f16<false, true><<<gemm_blocks, 512, SM_TOT>>>(
        bufB, wsp + 3 * 16384, b4, nullptr, nullptr, nullptr, nullptr,
        nullptr, bat, out, NN);
}

// round 17
// speedup vs baseline: 1.6200x; 1.0278x over previous
#include <cuda_runtime.h>
#include <cuda_fp16.h>

#define NN 50000
#define HD 128
#define EE 640000
#define GG 128
#define NT 391                           // ceil(NN/128) row tiles
#define PGRID 148                        // persistent grid = #SMs

typedef unsigned int u32;
typedef unsigned short u16;
typedef unsigned long long u64;

// Inter-layer buffers (f16, 12.8 MB each).
__device__ __align__(16) u16 g_bufA[NN * HD];
__device__ __align__(16) u16 g_bufB[NN * HD];
__device__ __align__(16) u16 g_bufC[NN * HD];
// Pre-converted W: [layer][16384 halves] (f16, transposed, swizzled image).
__device__ __align__(16) u16 g_wsp[4 * 16384];
// CSR-by-dst scratch
__device__ int g_rp[NN + 1];
__device__ int g_cur[NN];
__device__ int g_ssrc[EE];
__device__ int g_bsum[256];

#define SCAN_B 196

__device__ __forceinline__ u32 smem_u32(const void* p) {
    u32 a;
    asm("{ .reg .u64 t; cvta.to.shared.u64 t, %1; cvt.u32.u64 %0, t; }"
        : "=r"(a) : "l"(p));
    return a;
}
__device__ __forceinline__ void mma_f16(float* d, const u32* a, const u32* b) {
    asm("mma.sync.aligned.m16n8k16.row.col.f32.f16.f16.f32 "
        "{%0,%1,%2,%3}, {%4,%5,%6,%7}, {%8,%9}, {%0,%1,%2,%3};"
        : "+f"(d[0]), "+f"(d[1]), "+f"(d[2]), "+f"(d[3])
        : "r"(a[0]), "r"(a[1]), "r"(a[2]), "r"(a[3]), "r"(b[0]), "r"(b[1]));
}
__device__ __forceinline__ void ldsm4(u32* r, u32 addr) {
    asm volatile("ldmatrix.sync.aligned.m8n8.x4.shared.b16 {%0,%1,%2,%3}, [%4];"
                 : "=r"(r[0]), "=r"(r[1]), "=r"(r[2]), "=r"(r[3]) : "r"(addr));
}
__device__ __forceinline__ void cp16(u32 smem, const void* g) {
    asm volatile("cp.async.cg.shared.global [%0], [%1], 16;"
                 :: "r"(smem), "l"(g) : "memory");
}
__device__ __forceinline__ void cp_commit() {
    asm volatile("cp.async.commit_group;" ::: "memory");
}
__device__ __forceinline__ void cp_wait0() {
    asm volatile("cp.async.wait_group 0;" ::: "memory");
}
__device__ __forceinline__ void cp_wait1() {
    asm volatile("cp.async.wait_group 1;" ::: "memory");
}
__device__ __forceinline__ int swz_idx(int r, int kh) {
    return r * 32 + ((((kh >> 3) ^ ((r >> 1) & 3)) << 3) | (kh & 7));
}
__device__ __forceinline__ u32 pack_h2(float v0, float v1) {
    __half h0 = __float2half_rn(v0), h1 = __float2half_rn(v1);
    return (u32)__half_as_ushort(h0) | ((u32)__half_as_ushort(h1) << 16);
}
__device__ __forceinline__ float4 h4_to_f4(u64 v) {
    u32 lo = (u32)v, hi = (u32)(v >> 32);
    float2 f0 = __half22float2(*(__half2*)&lo);
    float2 f1 = __half22float2(*(__half2*)&hi);
    return make_float4(f0.x, f0.y, f1.x, f1.y);
}
__device__ __forceinline__ u64 f4_to_h4(float4 v) {
    return (u64)pack_h2(v.x, v.y) | ((u64)pack_h2(v.z, v.w) << 32);
}

// ---------------------------------------------------------------------------
// W prep: f16 convert, transposed [n][k], k-chunked (4x32), swizzled.
// ---------------------------------------------------------------------------
__global__ void prep_w(const float* __restrict__ W1, const float* __restrict__ W2,
                       const float* __restrict__ W3, const float* __restrict__ W4,
                       u16* __restrict__ out)
{
    int t = blockIdx.x * 256 + threadIdx.x;
    int layer = t >> 14, e = t & 16383;
    int k = e >> 7, n = e & 127;
    const float* W = layer == 0 ? W1 : layer == 1 ? W2 : layer == 2 ? W3 : W4;
    float v = W[k * HD + n];
    int ch = k >> 5, kh = k & 31;
    out[layer * 16384 + ch * 4096 + swz_idx(n, kh)] =
        __half_as_ushort(__float2half_rn(v));
}

// ---------------------------------------------------------------------------
// CSR build
// ---------------------------------------------------------------------------
__global__ void csr_zero(int* __restrict__ cnt)
{
    int t = blockIdx.x * blockDim.x + threadIdx.x;
    if (t < NN) cnt[t] = 0;
}
__global__ void csr_hist(const int* __restrict__ ei, int* __restrict__ cnt)
{
    int e = blockIdx.x * blockDim.x + threadIdx.x;
    if (e < EE) atomicAdd(cnt + __ldg(ei + 2 * e + 1), 1);
}
__global__ void csr_scan1(const int* __restrict__ cnt, int* __restrict__ bsum)
{
    __shared__ int s[256];
    int t = threadIdx.x, i = blockIdx.x * 256 + t;
    s[t] = (i < NN) ? cnt[i] : 0;
    __syncthreads();
    for (int o = 128; o > 0; o >>= 1) {
        if (t < o) s[t] += s[t + o];
        __syncthreads();
    }
    if (t == 0) bsum[blockIdx.x] = s[0];
}
__global__ void csr_scan2(int* __restrict__ bsum, int* __restrict__ rp)
{
    if (threadIdx.x == 0) {
        int run = 0;
        for (int b = 0; b < SCAN_B; b++) {
            int v = bsum[b];
            bsum[b] = run;
            run += v;
        }
        rp[NN] = run;
    }
}
__global__ void csr_scan3(const int* __restrict__ cnt, const int* __restrict__ bsum,
                          int* __restrict__ rp, int* __restrict__ cur)
{
    __shared__ int s[256];
    int t = threadIdx.x, i = blockIdx.x * 256 + t;
    int c = (i < NN) ? cnt[i] : 0;
    s[t] = c;
    __syncthreads();
    for (int o = 1; o < 256; o <<= 1) {
        int v = (t >= o) ? s[t - o] : 0;
        __syncthreads();
        s[t] += v;
        __syncthreads();
    }
    if (i < NN) {
        int excl = bsum[blockIdx.x] + s[t] - c;
        rp[i] = excl;
        cur[i] = excl;
    }
}
__global__ void csr_place(const int* __restrict__ ei, int* __restrict__ cur,
                          int* __restrict__ ssrc)
{
    int e = blockIdx.x * blockDim.x + threadIdx.x;
    if (e >= EE) return;
    int src = __ldg(ei + 2 * e);
    int dst = __ldg(ei + 2 * e + 1);
    int pos = atomicAdd(cur + dst, 1);
    ssrc[pos] = src;
}

// ---------------------------------------------------------------------------
// Atomic-free aggregate (f16 in/out, fp32 accumulate).
// ---------------------------------------------------------------------------
__global__ void __launch_bounds__(256) csr_agg(
    const u16* __restrict__ h, const int* __restrict__ rp,
    const int* __restrict__ ssrc, u16* __restrict__ out)
{
    int d = (blockIdx.x * blockDim.x + threadIdx.x) >> 5;
    if (d >= NN) return;
    int lane = threadIdx.x & 31;
    float4 acc = h4_to_f4(__ldg((const u64*)(h + (size_t)d * HD) + lane));
    int e = __ldg(rp + d), e1 = __ldg(rp + d + 1);
    for (; e + 4 <= e1; e += 4) {
        int s0 = __ldg(ssrc + e + 0);
        int s1 = __ldg(ssrc + e + 1);
        int s2 = __ldg(ssrc + e + 2);
        int s3 = __ldg(ssrc + e + 3);
        float4 v0 = h4_to_f4(__ldg((const u64*)(h + (size_t)s0 * HD) + lane));
        float4 v1 = h4_to_f4(__ldg((const u64*)(h + (size_t)s1 * HD) + lane));
        float4 v2 = h4_to_f4(__ldg((const u64*)(h + (size_t)s2 * HD) + lane));
        float4 v3 = h4_to_f4(__ldg((const u64*)(h + (size_t)s3 * HD) + lane));
        acc.x += (v0.x + v1.x) + (v2.x + v3.x);
        acc.y += (v0.y + v1.y) + (v2.y + v3.y);
        acc.z += (v0.z + v1.z) + (v2.z + v3.z);
        acc.w += (v0.w + v1.w) + (v2.w + v3.w);
    }
    for (; e < e1; ++e) {
        int s = __ldg(ssrc + e);
        float4 v = h4_to_f4(__ldg((const u64*)(h + (size_t)s * HD) + lane));
        acc.x += v.x; acc.y += v.y; acc.z += v.z; acc.w += v.w;
    }
    ((u64*)(out + (size_t)d * HD))[lane] = f4_to_h4(acc);
}

// ---------------------------------------------------------------------------
// Smem layouts
// ---------------------------------------------------------------------------
// Persistent single GEMM (G3): params + W + double-buffered A.
#define P_BB  0
#define P_SC  512
#define P_OF  1024
#define P_W   1536
#define P_A0  (P_W + 32768)              // 34304
#define P_A1  (P_A0 + 32768)             // 67072
#define P_TOT (P_A1 + 32768)             // 99840

// Persistent fused G1+G2: params + W1 + W2 + double-buffered A.
#define F_BB1 0
#define F_SC  512
#define F_OF  1024
#define F_BB2 1536
#define F_W1  2048
#define F_W2  (F_W1 + 32768)
#define F_A0  (F_W2 + 32768)             // 67584
#define F_A1  (F_A0 + 32768)             // 100352
#define F_TOT (F_A1 + 32768)             // 133120

// Non-persistent SEG GEMM (G4): same layout as R16.
#define SM_BB  0
#define SM_SC  512
#define SM_OF  1024
#define SM_W   1536
#define SM_A   (SM_W + 32768)
#define RED_STRIDE 132
#define SM_BATCH (SM_W + 128 * RED_STRIDE * 4)
#define SM_TOT (SM_BATCH + 512)          // 69632

// Single-pass f16 mainloop: 8 k16-steps, A at abase0, W at wbase0.
#define MAINLOOP(d, abase0, wbase0)                                           \
    _Pragma("unroll")                                                         \
    for (int ch = 0; ch < 4; ++ch) {                                          \
        const u32 abase = (abase0) + ch * 8192;                               \
        const u32 wbase = (wbase0) + ch * 8192;                               \
        _Pragma("unroll")                                                     \
        for (int s = 0; s < 2; ++s) {                                         \
            u32 fa[2][4];                                                     \
            const int ar = wm * 32 + (lane & 7) + ((lane & 8) ? 8 : 0);       \
            const int aj = s * 2 + ((lane & 16) ? 1 : 0);                     \
            _Pragma("unroll")                                                 \
            for (int mt = 0; mt < 2; mt++) {                                  \
                int r = ar + mt * 16;                                         \
                u32 off = (u32)(r * 64 + ((aj ^ ((r >> 1) & 3)) << 4));       \
                ldsm4(fa[mt], abase + off);                                   \
            }                                                                 \
            u32 fb[4][2];                                                     \
            const int brb = wn * 32 + ((lane & 16) ? 8 : 0) + (lane & 7);     \
            const int bj = s * 2 + ((lane & 8) ? 1 : 0);                      \
            _Pragma("unroll")                                                 \
            for (int t = 0; t < 2; t++) {                                     \
                int r = brb + t * 16;                                         \
                u32 off = (u32)(r * 64 + ((bj ^ ((r >> 1) & 3)) << 4));       \
                u32 tmp[4];                                                   \
                ldsm4(tmp, wbase + off);                                      \
                fb[2 * t][0] = tmp[0]; fb[2 * t][1] = tmp[1];                 \
                fb[2 * t + 1][0] = tmp[2]; fb[2 * t + 1][1] = tmp[3];         \
            }                                                                 \
            _Pragma("unroll")                                                 \
            for (int mt = 0; mt < 2; mt++)                                    \
                _Pragma("unroll")                                             \
                for (int nt = 0; nt < 4; nt++)                                \
                    mma_f16(d[mt][nt], fa[mt], fb[nt]);                       \
        }                                                                     \
    }

#define ZERO_D(d)                                                             \
    _Pragma("unroll")                                                         \
    for (int mt = 0; mt < 2; mt++)                                            \
        _Pragma("unroll")                                                     \
        for (int nt = 0; nt < 4; nt++)                                        \
            _Pragma("unroll")                                                 \
            for (int c = 0; c < 4; c++) (d)[mt][nt][c] = 0.f;

// Stage one f16 A tile (rows tile*128..+127) into smem via cp.async.
#define STAGE_F16(Aptr, tile, abuf)                                           \
    _Pragma("unroll")                                                         \
    for (int i = 0; i < 4; i++) {                                             \
        int idx = tid + i * 512;                                              \
        int r = idx >> 4;                                                     \
        int kh8 = (idx & 15) * 8;                                             \
        int chx = kh8 >> 5;                                                   \
        int khin = kh8 & 31;                                                  \
        u32 off = (abuf) + chx * 8192 + (u32)swz_idx(r, khin) * 2;            \
        int grow = (tile) * 128 + r;                                          \
        if (grow < M)                                                         \
            cp16(off, (Aptr) + (size_t)grow * HD + kh8);                      \
        else                                                                  \
            *(float4*)(sm + (off - sb)) = make_float4(0.f, 0.f, 0.f, 0.f);    \
    }

// ---------------------------------------------------------------------------
// Persistent fused layers 1+2: bufB(f16) = relu(bn1(relu(x@W1+b1))@W2+b2).
// x fp32, converted during staging; cross-tile double-buffered staging.
// ---------------------------------------------------------------------------
__global__ void __launch_bounds__(512, 1) gemm12_p(
    const float* __restrict__ A, const u16* __restrict__ w1sp,
    const u16* __restrict__ w2sp,
    const float* __restrict__ b1, const float* __restrict__ gam,
    const float* __restrict__ bet, const float* __restrict__ mmean,
    const float* __restrict__ mvar, const float* __restrict__ b2,
    u16* __restrict__ out, int M)
{
    extern __shared__ char sm[];
    const u32 sb = smem_u32(sm);
    float* const bb1 = (float*)(sm + F_BB1);
    float* const scp = (float*)(sm + F_SC);
    float* const ofp = (float*)(sm + F_OF);
    float* const bb2 = (float*)(sm + F_BB2);

    const int tid = threadIdx.x, wid = tid >> 5, lane = tid & 31;
    const int g = lane >> 2, q = lane & 3;
    const int wm = wid & 3, wn = wid >> 2;

    if (tid < 128) {
        bb1[tid] = b1[tid];
        float s = gam[tid] * rsqrtf(mvar[tid] + 1e-3f);
        scp[tid] = s;
        ofp[tid] = bet[tid] - mmean[tid] * s;
        bb2[tid] = b2[tid];
    }
#pragma unroll
    for (int i = 0; i < 4; i++) {
        int idx = tid + i * 512;
        cp16(sb + F_W1 + idx * 16, (const char*)w1sp + idx * 16);
        cp16(sb + F_W2 + idx * 16, (const char*)w2sp + idx * 16);
    }

    // fp32 -> f16 staging of x (not cp.async-able; regular loads+converts).
    auto stage_x = [&](int tile, u32 abuf) {
        const int j4 = lane * 4;
        const int chx = lane >> 3;
        const int kh = j4 & 31;
#pragma unroll
        for (int i = 0; i < 8; i++) {
            int r = wid * 8 + i;
            int grow = tile * 128 + r;
            float4 v = make_float4(0.f, 0.f, 0.f, 0.f);
            if (grow < M)
                v = *(const float4*)(A + (size_t)grow * HD + j4);
            int hidx = swz_idx(r, kh);
            *(u32*)(sm + (abuf - sb) + chx * 8192 + hidx * 2) = pack_h2(v.x, v.y);
            *(u32*)(sm + (abuf - sb) + chx * 8192 + hidx * 2 + 4) = pack_h2(v.z, v.w);
        }
    };

    const int q2 = q * 2;
    // W copy is async; x staging is synchronous stores. Wait for W once.
    cp_commit();
    cp_wait0();

    stage_x(blockIdx.x, sb + F_A0);
    __syncthreads();

    int b = 0;
    for (int tile = blockIdx.x; tile < NT; tile += PGRID, b ^= 1) {
        const u32 abuf = sb + (b ? F_A1 : F_A0);
        float d[2][4][4];
        ZERO_D(d);
        MAINLOOP(d, abuf, sb + F_W1);

        // Mid-epilogue: bn1(relu(.+b1)) -> f16 restage in place.
        __syncthreads();
#pragma unroll
        for (int mt = 0; mt < 2; mt++) {
            int lr = wm * 32 + mt * 16 + g;
#pragma unroll
            for (int nt = 0; nt < 4; nt++) {
                int col = wn * 32 + nt * 8 + q2;
                float s0 = scp[col], s1 = scp[col + 1];
                float o0 = ofp[col], o1 = ofp[col + 1];
                float B0 = bb1[col], B1 = bb1[col + 1];
                float v0 = fmaxf(d[mt][nt][0] + B0, 0.f) * s0 + o0;
                float v1 = fmaxf(d[mt][nt][1] + B1, 0.f) * s1 + o1;
                float v2 = fmaxf(d[mt][nt][2] + B0, 0.f) * s0 + o0;
                float v3 = fmaxf(d[mt][nt][3] + B1, 0.f) * s1 + o1;
                int chx = col >> 5, kh = col & 31;
                *(u32*)(sm + (abuf - sb) + chx * 8192 + swz_idx(lr, kh) * 2) =
                    pack_h2(v0, v1);
                *(u32*)(sm + (abuf - sb) + chx * 8192 + swz_idx(lr + 8, kh) * 2) =
                    pack_h2(v2, v3);
            }
        }
        ZERO_D(d);
        __syncthreads();

        MAINLOOP(d, abuf, sb + F_W2);
        __syncthreads();             // buf reads done before next restage cycle

        // Prefetch-equivalent for next tile (synchronous stores into other buf;
        // runs while this tile's stores below drain).
        int nxt = tile + PGRID;
        if (nxt < NT) stage_x(nxt, sb + (b ? F_A0 : F_A1));

        // Final epilogue: relu(.+b2) -> f16 out.
        int row0 = tile * 128;
#pragma unroll
        for (int mt = 0; mt < 2; mt++) {
            int r0 = row0 + wm * 32 + mt * 16 + g;
#pragma unroll
            for (int nt = 0; nt < 4; nt++) {
                int col = wn * 32 + nt * 8 + q2;
                float B0 = bb2[col], B1 = bb2[col + 1];
                float v0 = fmaxf(d[mt][nt][0] + B0, 0.f);
                float v1 = fmaxf(d[mt][nt][1] + B1, 0.f);
                float v2 = fmaxf(d[mt][nt][2] + B0, 0.f);
                float v3 = fmaxf(d[mt][nt][3] + B1, 0.f);
                if (r0 < M)
                    *(u32*)(out + (size_t)r0 * HD + col) = pack_h2(v0, v1);
                if (r0 + 8 < M)
                    *(u32*)(out + (size_t)(r0 + 8) * HD + col) = pack_h2(v2, v3);
            }
        }
        __syncthreads();             // staging of next tile complete for all
    }
}

// ---------------------------------------------------------------------------
// Persistent single f16 GEMM (G3): out = bn(relu(A@W+bias)). Double-buffered
// cp.async A staging across tiles; W resident.
// ---------------------------------------------------------------------------
__global__ void __launch_bounds__(512, 1) gemm_p(
    const u16* __restrict__ A, const u16* __restrict__ wsp,
    const float* __restrict__ bias, const float* __restrict__ gam,
    const float* __restrict__ bet, const float* __restrict__ mmean,
    const float* __restrict__ mvar, u16* __restrict__ out, int M)
{
    extern __shared__ char sm[];
    const u32 sb = smem_u32(sm);
    float* const bbp = (float*)(sm + P_BB);
    float* const scp = (float*)(sm + P_SC);
    float* const ofp = (float*)(sm + P_OF);

    const int tid = threadIdx.x, wid = tid >> 5, lane = tid & 31;
    const int g = lane >> 2, q = lane & 3;
    const int wm = wid & 3, wn = wid >> 2;

    if (tid < 128) {
        bbp[tid] = bias[tid];
        float s = gam[tid] * rsqrtf(mvar[tid] + 1e-3f);
        scp[tid] = s;
        ofp[tid] = bet[tid] - mmean[tid] * s;
    }
#pragma unroll
    for (int i = 0; i < 4; i++) {
        int idx = tid + i * 512;
        cp16(sb + P_W + idx * 16, (const char*)wsp + idx * 16);
    }
    // Group 0: W + first A tile.
    STAGE_F16(A, (int)blockIdx.x, sb + P_A0);
    cp_commit();

    const int q2 = q * 2;
    int b = 0;
    for (int tile = blockIdx.x; tile < NT; tile += PGRID, b ^= 1) {
        int nxt = tile + PGRID;
        if (nxt < NT) {
            STAGE_F16(A, nxt, sb + (b ? P_A0 : P_A1));
            cp_commit();
            cp_wait1();              // current tile's group complete
        } else {
            cp_wait0();
        }
        __syncthreads();

        const u32 abuf = sb + (b ? P_A1 : P_A0);
        float d[2][4][4];
        ZERO_D(d);
        MAINLOOP(d, abuf, sb + P_W);
        __syncthreads();             // buf reads done before it is re-staged

        int row0 = tile * 128;
#pragma unroll
        for (int mt = 0; mt < 2; mt++) {
            int r0 = row0 + wm * 32 + mt * 16 + g;
#pragma unroll
            for (int nt = 0; nt < 4; nt++) {
                int col = wn * 32 + nt * 8 + q2;
                float s0 = scp[col], s1 = scp[col + 1];
                float o0 = ofp[col], o1 = ofp[col + 1];
                float B0 = bbp[col], B1 = bbp[col + 1];
                float v0 = fmaxf(d[mt][nt][0] + B0, 0.f) * s0 + o0;
                float v1 = fmaxf(d[mt][nt][1] + B1, 0.f) * s1 + o1;
                float v2 = fmaxf(d[mt][nt][2] + B0, 0.f) * s0 + o0;
                float v3 = fmaxf(d[mt][nt][3] + B1, 0.f) * s1 + o1;
                if (r0 < M)
                    *(u32*)(out + (size_t)r0 * HD + col) = pack_h2(v0, v1);
                if (r0 + 8 < M)
                    *(u32*)(out + (size_t)(r0 + 8) * HD + col) = pack_h2(v2, v3);
            }
        }
    }
}

// ---------------------------------------------------------------------------
// Non-persistent G4 + fused segment-sum (as in R16): gout += segsum(relu(A@W+b)).
// ---------------------------------------------------------------------------
__global__ void __launch_bounds__(512, 1) gemm_seg(
    const u16* __restrict__ A, const u16* __restrict__ wsp,
    const float* __restrict__ bias, const int* __restrict__ batch,
    float* __restrict__ gout, int M)
{
    extern __shared__ char sm[];
    const u32 sb = smem_u32(sm);
    float* const bbp = (float*)(sm + SM_BB);

    const int tid = threadIdx.x, wid = tid >> 5, lane = tid & 31;
    const int g = lane >> 2, q = lane & 3;
    const int wm = wid & 3, wn = wid >> 2;
    const int row0 = blockIdx.x * 128;

    if (tid < 128) bbp[tid] = bias[tid];
#pragma unroll
    for (int i = 0; i < 4; i++) {
        int idx = tid + i * 512;
        cp16(sb + SM_W + idx * 16, (const char*)wsp + idx * 16);
    }
#pragma unroll
    for (int i = 0; i < 4; i++) {
        int idx = tid + i * 512;
        int r = idx >> 4;
        int kh8 = (idx & 15) * 8;
        int chx = kh8 >> 5;
        int khin = kh8 & 31;
        u32 off = SM_A + chx * 8192 + (u32)swz_idx(r, khin) * 2;
        int grow = row0 + r;
        if (grow < M)
            cp16(sb + off, A + (size_t)grow * HD + kh8);
        else
            *(float4*)(sm + off) = make_float4(0.f, 0.f, 0.f, 0.f);
    }

    float d[2][4][4];
    ZERO_D(d);
    cp_commit();
    cp_wait0();
    __syncthreads();

    MAINLOOP(d, sb + SM_A, sb + SM_W);

    const int q2 = q * 2;
    float* red = (float*)(sm + SM_W);
    int* bsm = (int*)(sm + SM_BATCH);
    __syncthreads();
#pragma unroll
    for (int mt = 0; mt < 2; mt++) {
        int lr = wm * 32 + mt * 16 + g;
        bool ok0 = (row0 + lr < M), ok1 = (row0 + lr + 8 < M);
#pragma unroll
        for (int nt = 0; nt < 4; nt++) {
            int col = wn * 32 + nt * 8 + q2;
            float B0 = bbp[col], B1 = bbp[col + 1];
            float v0 = ok0 ? fmaxf(d[mt][nt][0] + B0, 0.f) : 0.f;
            float v1 = ok0 ? fmaxf(d[mt][nt][1] + B1, 0.f) : 0.f;
            float v2 = ok1 ? fmaxf(d[mt][nt][2] + B0, 0.f) : 0.f;
            float v3 = ok1 ? fmaxf(d[mt][nt][3] + B1, 0.f) : 0.f;
            *(float2*)&red[lr * RED_STRIDE + col] = make_float2(v0, v1);
            *(float2*)&red[(lr + 8) * RED_STRIDE + col] = make_float2(v2, v3);
        }
    }
    if (tid < 128)
        bsm[tid] = (row0 + tid < M) ? __ldg(batch + row0 + tid) : -1;
    __syncthreads();
    const int c = tid & 127, part = tid >> 7;
    const int rb = part * 32;
    float acc = 0.f;
    int curb = bsm[rb];
#pragma unroll
    for (int r = 0; r < 32; ++r) {
        int bb = bsm[rb + r];
        if (bb != curb) {
            if (curb >= 0) atomicAdd(gout + (size_t)curb * HD + c, acc);
            acc = 0.f;
            curb = bb;
        }
        acc += red[(rb + r) * RED_STRIDE + c];
    }
    if (curb >= 0) atomicAdd(gout + (size_t)curb * HD + c, acc);
}

__global__ void zero_out(float* __restrict__ out, int n)
{
    int t = blockIdx.x * blockDim.x + threadIdx.x;
    if (t < n) out[t] = 0.f;
}

extern "C" void kernel_launch(void* const* d_in, const int* in_sizes, int n_in,
                              void* d_out, int out_size)
{
    const float* x   = (const float*)d_in[0];
    const int*   ei  = (const int*)d_in[1];
    const int*   bat = (const int*)d_in[2];
    const float* W1  = (const float*)d_in[3];
    const float* b1  = (const float*)d_in[4];
    const float* g1  = (const float*)d_in[5];
    const float* be1 = (const float*)d_in[6];
    const float* mm1 = (const float*)d_in[7];
    const float* mv1 = (const float*)d_in[8];
    const float* W2  = (const float*)d_in[9];
    const float* b2  = (const float*)d_in[10];
    const float* W3  = (const float*)d_in[11];
    const float* b3  = (const float*)d_in[12];
    const float* g2  = (const float*)d_in[13];
    const float* be2 = (const float*)d_in[14];
    const float* mm2 = (const float*)d_in[15];
    const float* mv2 = (const float*)d_in[16];
    const float* W4  = (const float*)d_in[17];
    const float* b4  = (const float*)d_in[18];
    float* out = (float*)d_out;

    u16 *bufA, *bufB, *bufC, *wsp;
    int *rp, *cur, *ssrc, *bsum;
    cudaGetSymbolAddress((void**)&bufA, g_bufA);
    cudaGetSymbolAddress((void**)&bufB, g_bufB);
    cudaGetSymbolAddress((void**)&bufC, g_bufC);
    cudaGetSymbolAddress((void**)&wsp, g_wsp);
    cudaGetSymbolAddress((void**)&rp, g_rp);
    cudaGetSymbolAddress((void**)&cur, g_cur);
    cudaGetSymbolAddress((void**)&ssrc, g_ssrc);
    cudaGetSymbolAddress((void**)&bsum, g_bsum);

    cudaFuncSetAttribute(gemm12_p,
                         cudaFuncAttributeMaxDynamicSharedMemorySize, F_TOT);
    cudaFuncSetAttribute(gemm_p,
                         cudaFuncAttributeMaxDynamicSharedMemorySize, P_TOT);
    cudaFuncSetAttribute(gemm_seg,
                         cudaFuncAttributeMaxDynamicSharedMemorySize, SM_TOT);

    static cudaStream_t s2 = nullptr;
    static cudaEvent_t evFork = nullptr, evJoin = nullptr;
    if (s2 == nullptr) {
        cudaStreamCreateWithFlags(&s2, cudaStreamNonBlocking);
        cudaEventCreateWithFlags(&evFork, cudaEventDisableTiming);
        cudaEventCreateWithFlags(&evJoin, cudaEventDisableTiming);
    }

    const int edge_blocks = (EE + 255) / 256;
    const int agg_blocks  = (NN * 32 + 255) / 256;

    // Main: W prep; fork CSR build + output zeroing to s2 (evJoin AFTER
    // zero_out so the fused seg atomics are ordered after the zeroing).
    prep_w<<<256, 256>>>(W1, W2, W3, W4, wsp);
    cudaEventRecord(evFork, 0);
    cudaStreamWaitEvent(s2, evFork, 0);
    csr_zero<<<(NN + 255) / 256, 256, 0, s2>>>(cur);
    csr_hist<<<edge_blocks, 256, 0, s2>>>(ei, cur);
    csr_scan1<<<SCAN_B, 256, 0, s2>>>(cur, bsum);
    csr_scan2<<<1, 32, 0, s2>>>(bsum, rp);
    csr_scan3<<<SCAN_B, 256, 0, s2>>>(cur, bsum, rp, cur);
    csr_place<<<edge_blocks, 256, 0, s2>>>(ei, cur, ssrc);
    zero_out<<<(GG * HD + 255) / 256, 256, 0, s2>>>(out, GG * HD);
    cudaEventRecord(evJoin, s2);

    // Fused layers 1+2 (persistent): x -> bufB(f16), overlaps CSR build.
    gemm12_p<<<PGRID, 512, F_TOT>>>(
        x, wsp + 0 * 16384, wsp + 1 * 16384,
        b1, g1, be1, mm1, mv1, b2, bufB, NN);

    // Join: csr_agg needs the CSR arrays (and transitively zero_out done).
    cudaStreamWaitEvent(0, evJoin, 0);

    // bufC = bufB + aggregate(bufB)
    csr_agg<<<agg_blocks, 256>>>(bufB, rp, ssrc, bufC);
    // bufA = bn2(relu(bufC@W3+b3))  (persistent, pipelined)
    gemm_p<<<PGRID, 512, P_TOT>>>(
        bufC, wsp + 2 * 16384, b3, g2, be2, mm2, mv2, bufA, NN);
    // bufB = bufA + aggregate(bufA)
    csr_agg<<<agg_blocks, 256>>>(bufA, rp, ssrc, bufB);
    // out += segsum(relu(bufB@W4+b4))  fused epilogue
    gemm_seg<<<NT, 512, SM_TOT>>>(bufB, wsp + 3 * 16384, b4, bat, out, NN);
}